// round 7
// baseline (speedup 1.0000x reference)
#include <cuda_runtime.h>

// Fixed shapes: B=32,S=256 -> NTOK=8192; D=16; V=8192; n_steps=8
#define NTOK 8192
#define DD   16
#define VV   8192
#define VC   128            // V-chunk staged in SMEM (double-buffered)
#define TPT  2              // tokens per thread (reg pressure: 2 CTAs/SM)
#define LANES 32
#define SLICE 8             // warps per CTA
#define NTHREADS 256
#define TPC (LANES*TPT)     // 64 tokens per CTA
#define NTB (NTOK/TPC)      // 128 token blocks
#define VSPLIT 2
#define VPER (VV/VSPLIT)    // 4096
#define NCHUNK (VPER/VC)    // 32
#define NBLOCKS (NTB*VSPLIT)// 256 CTAs -> one wave at 2 CTAs/SM

#define INVT  1.25f
#define LOG2E 1.4426950408889634f
#define LSCALE (INVT*LOG2E)

typedef unsigned long long u64;
typedef unsigned int u32;

// Scratch (allocation-free rule)
__device__ float g_x   [NTOK*DD];
__device__ float g_xm  [NTOK*DD];
__device__ float g_pack[VV*32];          // [v][0..15]=LSCALE*W[:,v], [v][16..31]=CB[v,:]
__device__ float g_part[VSPLIT*17*NTOK]; // per-slot partials
__device__ int   g_ticket[NTB];          // zero-init; reset by finalizer each launch

__device__ __forceinline__ float ex2f(float x) {
    float r; asm("ex2.approx.ftz.f32 %0, %1;" : "=f"(r) : "f"(x)); return r;
}
#define FMA2(d,a,b,c) asm("fma.rn.f32x2 %0, %1, %2, %3;" : "=l"(d) : "l"(a), "l"(b), "l"(c))
#define MUL2(d,a,b)   asm("mul.rn.f32x2 %0, %1, %2;"     : "=l"(d) : "l"(a), "l"(b))
#define ADD2(d,a,b)   asm("add.rn.f32x2 %0, %1, %2;"     : "=l"(d) : "l"(a), "l"(b))
#define UNPK2(lo,hi,v) asm("mov.b64 {%0,%1}, %2;" : "=f"(lo), "=f"(hi) : "l"(v))
#define PCK2(v,lo,hi)  asm("mov.b64 %0, {%1,%2};" : "=l"(v) : "f"(lo), "f"(hi))

#define CPA16(dst,src)  asm volatile("cp.async.cg.shared.global [%0],[%1],16;" :: "r"(dst), "l"(src))
#define CPA_COMMIT()    asm volatile("cp.async.commit_group;" ::: "memory")
#define CPA_WAIT0()     asm volatile("cp.async.wait_group 0;" ::: "memory")

__global__ void copy_kernel(const float* __restrict__ src, int n) {
    int i = blockIdx.x * blockDim.x + threadIdx.x;
    if (i < n) g_x[i] = src[i];
}

__global__ void prep_kernel(const float* __restrict__ W,   // [DD][VV]
                            const float* __restrict__ CB)  // [VV][DD]
{
    int v = blockIdx.x * blockDim.x + threadIdx.x;
    if (v >= VV) return;
    float wcol[DD];
    #pragma unroll
    for (int d = 0; d < DD; d++) wcol[d] = W[d*VV + v] * LSCALE;
    float4* dst = (float4*)(g_pack + v*32);
    const float4* cb = (const float4*)(CB + v*DD);
    #pragma unroll
    for (int i = 0; i < 4; i++) {
        float4 w4; w4.x=wcol[4*i]; w4.y=wcol[4*i+1]; w4.z=wcol[4*i+2]; w4.w=wcol[4*i+3];
        dst[i]   = w4;
        dst[4+i] = cb[i];
    }
}

// velocity = (softmax((x@W + b + t*tp)/T) @ CB - x)/(1-t+eps); x_out = g_x + coef*v
// No max-subtraction (|log2 logits| <~ 40, fp32-safe).
__global__ __launch_bounds__(NTHREADS, 2)
void velocity_kernel(const float* __restrict__ b,
                     const float* __restrict__ tp,
                     float t, float coef, int mode)
{
    __shared__ __align__(16) float buf[2][VC*32];   // 2 x 16KB double buffer
    __shared__ float csm[2][VC];
    __shared__ int flag;

    const float* x_in  = mode ? g_xm : g_x;
    float*       x_out = mode ? g_x  : g_xm;

    int tid   = threadIdx.x;
    int lane  = tid & 31;
    int slice = tid >> 5;                 // warp 0..7
    int tb    = blockIdx.x >> 1;          // token block 0..127
    int slot  = blockIdx.x & 1;           // V slot 0..1
    int tok0  = tb*TPC + lane;

    // 2 tokens' x as packed f32x2 pairs
    u64 xr[TPT][8], mur[TPT][8];
    u64 zero2; PCK2(zero2, 0.f, 0.f);
    float s[TPT];
    #pragma unroll
    for (int j = 0; j < TPT; j++) {
        const ulonglong2* A = (const ulonglong2*)(x_in + (tok0 + 32*j)*DD);
        #pragma unroll
        for (int i = 0; i < 4; i++) {
            ulonglong2 v2 = A[i];
            xr[j][2*i] = v2.x; xr[j][2*i+1] = v2.y;
        }
        #pragma unroll
        for (int i = 0; i < 8; i++) mur[j][i] = zero2;
        s[j] = 0.f;
    }

    int cbeg = slot * VPER;

    // Prologue: prefetch chunk 0 data + bias
    {
        u32 d0 = (u32)__cvta_generic_to_shared(&buf[0][0]) + tid*16;
        const char* s0 = (const char*)(g_pack + (size_t)cbeg*32) + tid*16;
        #pragma unroll
        for (int k = 0; k < 4; k++) CPA16(d0 + k*NTHREADS*16, s0 + k*NTHREADS*16);
        CPA_COMMIT();
    }
    float rb = 0.f, rtp = 0.f;
    if (tid < VC) { rb = b[cbeg+tid]; rtp = tp[cbeg+tid]; }

    for (int ci = 0; ci < NCHUNK; ci++) {
        int cur = ci & 1;
        CPA_WAIT0();                               // chunk ci landed in buf[cur]
        if (tid < VC) csm[cur][tid] = (rb + t*rtp) * LSCALE;
        __syncthreads();                           // csm visible; buf[cur^1] free

        if (ci + 1 < NCHUNK) {                     // prefetch chunk ci+1
            int c1 = cbeg + (ci+1)*VC;
            u32 d1 = (u32)__cvta_generic_to_shared(&buf[cur^1][0]) + tid*16;
            const char* s1 = (const char*)(g_pack + (size_t)c1*32) + tid*16;
            #pragma unroll
            for (int k = 0; k < 4; k++) CPA16(d1 + k*NTHREADS*16, s1 + k*NTHREADS*16);
            CPA_COMMIT();
            if (tid < VC) { rb = b[c1+tid]; rtp = tp[c1+tid]; }
        }

        const float* bufc = buf[cur];
        const float* csmc = csm[cur];
        int vbeg = slice * (VC/SLICE);             // 16 v per warp per chunk
        #pragma unroll 4
        for (int vi = 0; vi < VC/SLICE; vi++) {
            int v = vbeg + vi;
            const ulonglong2* p = (const ulonglong2*)(bufc + v*32); // warp-broadcast
            ulonglong2 P0=p[0], P1=p[1], P2=p[2], P3=p[3];
            float c = csmc[v];
            u64 cpair; PCK2(cpair, c, 0.f);
            float pw[TPT];
            // phase 1: parallel dot chains
            #pragma unroll
            for (int j = 0; j < TPT; j++) {
                u64 q0 = cpair, q1;
                FMA2(q0, xr[j][0], P0.x, q0);  MUL2(q1, xr[j][1], P0.y);
                FMA2(q0, xr[j][2], P1.x, q0);  FMA2(q1, xr[j][3], P1.y, q1);
                FMA2(q0, xr[j][4], P2.x, q0);  FMA2(q1, xr[j][5], P2.y, q1);
                FMA2(q0, xr[j][6], P3.x, q0);  FMA2(q1, xr[j][7], P3.y, q1);
                ADD2(q0, q0, q1);
                float lo, hi; UNPK2(lo, hi, q0);
                pw[j] = lo + hi;
            }
            ulonglong2 C0=p[4], C1=p[5], C2=p[6], C3=p[7];
            // phase 2: parallel ex2
            #pragma unroll
            for (int j = 0; j < TPT; j++) { pw[j] = ex2f(pw[j]); s[j] += pw[j]; }
            // phase 3: accumulate
            #pragma unroll
            for (int j = 0; j < TPT; j++) {
                u64 p2; PCK2(p2, pw[j], pw[j]);
                FMA2(mur[j][0], p2, C0.x, mur[j][0]); FMA2(mur[j][1], p2, C0.y, mur[j][1]);
                FMA2(mur[j][2], p2, C1.x, mur[j][2]); FMA2(mur[j][3], p2, C1.y, mur[j][3]);
                FMA2(mur[j][4], p2, C2.x, mur[j][4]); FMA2(mur[j][5], p2, C2.y, mur[j][5]);
                FMA2(mur[j][6], p2, C3.x, mur[j][6]); FMA2(mur[j][7], p2, C3.y, mur[j][7]);
            }
        }
        __syncthreads();                           // done with buf[cur] before it refills
    }

    // In-CTA slice reduction; write 17-float partial per token to global slot
    float* red = &buf[0][0];                       // 256*17 = 4352 floats, fits
    #pragma unroll
    for (int j = 0; j < TPT; j++) {
        __syncthreads();
        {
            float* r = red + tid*17;
            r[0] = s[j];
            #pragma unroll
            for (int i = 0; i < 8; i++) {
                float lo, hi; UNPK2(lo, hi, mur[j][i]);
                r[1+2*i] = lo; r[2+2*i] = hi;
            }
        }
        __syncthreads();
        if (slice == 0) {
            int tok = tok0 + 32*j;
            float S = 0.f, acc[DD];
            #pragma unroll
            for (int d = 0; d < DD; d++) acc[d] = 0.f;
            #pragma unroll
            for (int q = 0; q < SLICE; q++) {
                const float* r = red + (q*32 + lane)*17;
                S += r[0];
                #pragma unroll
                for (int d = 0; d < DD; d++) acc[d] += r[1+d];
            }
            g_part[(slot*17 + 0)*NTOK + tok] = S;
            #pragma unroll
            for (int d = 0; d < DD; d++)
                g_part[(slot*17 + 1 + d)*NTOK + tok] = acc[d];
        }
    }

    // Cross-CTA combine: last arriving CTA for this tokblock finalizes
    __threadfence();
    __syncthreads();
    if (tid == 0) flag = (atomicAdd(&g_ticket[tb], 1) == VSPLIT - 1);
    __syncthreads();
    if (flag) {
        __threadfence();
        if (tid < TPC) {
            int tok = tb*TPC + tid;
            float S = 0.f, acc[DD];
            #pragma unroll
            for (int d = 0; d < DD; d++) acc[d] = 0.f;
            #pragma unroll
            for (int q = 0; q < VSPLIT; q++) {       // fixed order -> deterministic
                S += __ldcg(&g_part[(q*17 + 0)*NTOK + tok]);
                #pragma unroll
                for (int d = 0; d < DD; d++)
                    acc[d] += __ldcg(&g_part[(q*17 + 1 + d)*NTOK + tok]);
            }
            float invS   = 1.f / S;
            float invden = 1.f / (1.f - t + 1e-10f);
            const float4* xi4 = (const float4*)(x_in + tok*DD);
            const float4* xb4 = (const float4*)(g_x  + tok*DD);
            float4 o[4]; float* of = (float*)o;
            #pragma unroll
            for (int i = 0; i < 4; i++) {
                float4 xi = xi4[i], xbs = xb4[i];
                float xiv[4] = {xi.x, xi.y, xi.z, xi.w};
                float xbv[4] = {xbs.x, xbs.y, xbs.z, xbs.w};
                #pragma unroll
                for (int jj = 0; jj < 4; jj++) {
                    int d = 4*i + jj;
                    of[d] = fmaf(coef, (acc[d]*invS - xiv[jj]) * invden, xbv[jj]);
                }
            }
            float4* xo4 = (float4*)(x_out + tok*DD);
            #pragma unroll
            for (int i = 0; i < 4; i++) xo4[i] = o[i];
        }
        if (tid == 0) g_ticket[tb] = 0;   // clean for next launch / replay
    }
}

// VQ argmin_v ||c_v||^2 - 2 x.c_v
__global__ __launch_bounds__(256)
void quantize_kernel(const float* __restrict__ CB,
                     float* __restrict__ out_x,
                     float* __restrict__ out_idx)
{
    __shared__ __align__(16) float smem[256*DD + 256];
    float* CBsm = smem;
    float* cn2  = smem + 256*DD;

    int tid   = threadIdx.x;
    int tokl  = tid & 63;
    int slice = tid >> 6;
    int tok   = blockIdx.x * 64 + tokl;

    float x[DD];
    {
        const float4* xi4 = (const float4*)(g_x + tok*DD);
        #pragma unroll
        for (int i = 0; i < 4; i++) {
            float4 v4 = xi4[i];
            x[4*i+0]=v4.x; x[4*i+1]=v4.y; x[4*i+2]=v4.z; x[4*i+3]=v4.w;
        }
    }

    float best = 3.4e38f;
    int   bidx = 0;

    for (int c0 = 0; c0 < VV; c0 += 256) {
        __syncthreads();
        {
            const float4* src = (const float4*)(CB + (size_t)c0*DD);
            float4* dst = (float4*)CBsm;
            for (int j = tid; j < 256*DD/4; j += 256) dst[j] = src[j];
        }
        {
            const float* row = CB + (size_t)(c0 + tid)*DD;
            float acc = 0.f;
            #pragma unroll
            for (int d = 0; d < DD; d++) acc = fmaf(row[d], row[d], acc);
            cn2[tid] = acc;
        }
        __syncthreads();

        int vbeg = slice * 64;
        for (int vi = 0; vi < 64; vi++) {
            int v = vbeg + vi;
            const float4* cb4 = (const float4*)(CBsm + v*DD);
            float4 cA=cb4[0], cB4=cb4[1], cC=cb4[2], cD4=cb4[3];
            float a0 = x[0]*cA.x  + x[1]*cA.y  + x[2]*cA.z  + x[3]*cA.w;
            float a1 = x[4]*cB4.x + x[5]*cB4.y + x[6]*cB4.z + x[7]*cB4.w;
            float a2 = x[8]*cC.x  + x[9]*cC.y  + x[10]*cC.z + x[11]*cC.w;
            float a3 = x[12]*cD4.x+ x[13]*cD4.y+ x[14]*cD4.z+ x[15]*cD4.w;
            float dist = cn2[v] - 2.f*((a0+a1) + (a2+a3));
            if (dist < best) { best = dist; bidx = c0 + v; }
        }
    }

    __syncthreads();
    float* redf = smem;
    redf[tid*2] = best;
    ((int*)redf)[tid*2 + 1] = bidx;
    __syncthreads();

    if (slice == 0) {
        float bb = best; int bi = bidx;
        #pragma unroll
        for (int q = 1; q < 4; q++) {
            float dq = redf[(tokl + 64*q)*2];
            int   iq = ((int*)redf)[(tokl + 64*q)*2 + 1];
            if (dq < bb || (dq == bb && iq < bi)) { bb = dq; bi = iq; }
        }
        if (out_idx) out_idx[tok] = (float)bi;
        if (out_x) {
            const float4* xi4 = (const float4*)(g_x + tok*DD);
            float4* o4 = (float4*)(out_x + tok*DD);
            #pragma unroll
            for (int i = 0; i < 4; i++) o4[i] = xi4[i];
        }
    }
}

extern "C" void kernel_launch(void* const* d_in, const int* in_sizes, int n_in,
                              void* d_out, int out_size) {
    const float* x0 = (const float*)d_in[0];
    const float* CB = (const float*)d_in[1];
    const float* W  = (const float*)d_in[2];
    const float* b  = (const float*)d_in[3];
    const float* tp = (const float*)d_in[4];

    copy_kernel<<<(NTOK*DD + 255)/256, 256>>>(x0, NTOK*DD);
    prep_kernel<<<VV/256, 256>>>(W, CB);

    const float dt = 1.0f / 7.0f;
    for (int k = 0; k < 7; k++) {
        float t = (float)k / 7.0f;
        velocity_kernel<<<NBLOCKS, NTHREADS>>>(b, tp, t,           0.5f*dt, 0);
        velocity_kernel<<<NBLOCKS, NTHREADS>>>(b, tp, t + 0.5f*dt, dt,      1);
    }

    float* out = (float*)d_out;
    if (out_size >= NTOK*DD + NTOK) {
        quantize_kernel<<<NTOK/64, 256>>>(CB, out, out + NTOK*DD);
    } else if (out_size == NTOK*DD) {
        quantize_kernel<<<NTOK/64, 256>>>(CB, out, nullptr);
    } else {
        quantize_kernel<<<NTOK/64, 256>>>(CB, nullptr, out);
    }
}

// round 8
// speedup vs baseline: 1.3269x; 1.3269x over previous
#include <cuda_runtime.h>

// Fixed shapes: B=32,S=256 -> NTOK=8192; D=16; V=8192; n_steps=8
#define NTOK 8192
#define DD   16
#define VV   8192
#define VC   64              // v per chunk (8 MMA tiles), double-buffered
#define NTHREADS 256
#define WARPS 8
#define TPC  128             // 8 warps x 16 tokens
#define NTB  (NTOK/TPC)      // 64 token blocks
#define VSPLIT 4
#define VPER (VV/VSPLIT)     // 2048
#define NCHUNK (VPER/VC)     // 32
#define NBLOCKS (NTB*VSPLIT) // 256 CTAs -> 2/SM, one wave
#define TPCH 8               // tiles per chunk
#define NTILES (VV/8)        // 1024 v-tiles

#define INVT  1.25f
#define LOG2E 1.4426950408889634f
#define LSCALE (INVT*LOG2E)

typedef unsigned int u32;

// Scratch (allocation-free rule)
__device__ float g_x [NTOK*DD];
__device__ float g_xm[NTOK*DD];
// Fragment pack: per v-tile: [kind][lane][4] floats, kind: 0=Whi 1=Wlo 2=CBhi 3=CBlo
__device__ float g_frag[NTILES*512];
__device__ float g_part[VSPLIT*17*NTOK];
__device__ int   g_ticket[NTB];

__device__ __forceinline__ float ex2f(float x) {
    float r; asm("ex2.approx.ftz.f32 %0, %1;" : "=f"(r) : "f"(x)); return r;
}
__device__ __forceinline__ u32 tf32hi(float f) {
    u32 r; asm("cvt.rna.tf32.f32 %0, %1;" : "=r"(r) : "f"(f)); return r;
}
// D(+=C) = A(m16k8,tf32) * B(k8n8,tf32), fp32 accum, in-place accumulator
#define MMA(d0,d1,d2,d3,a0,a1,a2,a3,b0,b1) \
    asm("mma.sync.aligned.m16n8k8.row.col.f32.tf32.tf32.f32 " \
        "{%0,%1,%2,%3},{%4,%5,%6,%7},{%8,%9},{%0,%1,%2,%3};" \
        : "+f"(d0),"+f"(d1),"+f"(d2),"+f"(d3) \
        : "r"(a0),"r"(a1),"r"(a2),"r"(a3),"r"(b0),"r"(b1))

#define CPA16(dst,src)  asm volatile("cp.async.cg.shared.global [%0],[%1],16;" :: "r"(dst), "l"(src))
#define CPA_COMMIT()    asm volatile("cp.async.commit_group;" ::: "memory")
#define CPA_WAIT0()     asm volatile("cp.async.wait_group 0;" ::: "memory")

__global__ void copy_kernel(const float* __restrict__ src, int n) {
    int i = blockIdx.x * blockDim.x + threadIdx.x;
    if (i < n) g_x[i] = src[i];
}

// Pre-bake W (scaled, hi/lo) and CB (hi/lo) into exact mma B-fragment layout.
__global__ void prep_frag(const float* __restrict__ W,   // [DD][VV]
                          const float* __restrict__ CB)  // [VV][DD]
{
    int gid  = blockIdx.x * blockDim.x + threadIdx.x;   // NTILES*32 threads
    int tile = gid >> 5;
    int lane = gid & 31;
    if (tile >= NTILES) return;
    int g   = lane >> 2;
    int tig = lane & 3;
    int v0  = tile * 8;
    float* out = g_frag + tile*512 + lane*4;

    // W' = W * LSCALE ; B-frag k rows: kt0:{tig,tig+4}, kt1:{tig+8,tig+12}; col v0+g
    int ks[4] = {tig, tig+4, tig+8, tig+12};
    #pragma unroll
    for (int j = 0; j < 4; j++) {
        float wv = W[ks[j]*VV + (v0+g)] * LSCALE;
        u32 hb = tf32hi(wv);
        float hf = __uint_as_float(hb);
        out[      j] = hf;        // kind 0: Whi
        out[128 + j] = wv - hf;   // kind 1: Wlo
    }
    // CB B-frag: k rows v0+tig / v0+tig+4; cols d=g (nt0), d=8+g (nt1)
    int vr0 = v0 + tig, vr1 = v0 + tig + 4;
    float cv[4] = { CB[vr0*DD + g],     CB[vr1*DD + g],
                    CB[vr0*DD + 8 + g], CB[vr1*DD + 8 + g] };
    #pragma unroll
    for (int j = 0; j < 4; j++) {
        u32 hb = tf32hi(cv[j]);
        float hf = __uint_as_float(hb);
        out[256 + j] = hf;        // kind 2: CBhi
        out[384 + j] = cv[j] - hf;// kind 3: CBlo
    }
}

// velocity = (softmax((x@W + b + t*tp)/T) @ CB - x)/(1-t+eps); x_out = g_x + coef*v
// tf32 MMA with hi/lo split everywhere -> fp32-class accuracy. No max-subtraction.
__global__ __launch_bounds__(NTHREADS, 2)
void velocity_kernel(const float* __restrict__ b,
                     const float* __restrict__ tp,
                     float t, float coef, int mode)
{
    __shared__ __align__(16) float buf[2][TPCH*512];   // 2 x 16KB frag chunks
    __shared__ float csm[2][VC];
    __shared__ int flag;

    const float* x_in  = mode ? g_xm : g_x;
    float*       x_out = mode ? g_x  : g_xm;

    int tid  = threadIdx.x;
    int lane = tid & 31;
    int warp = tid >> 5;
    int g    = lane >> 2;
    int tig  = lane & 3;
    int tb   = blockIdx.x >> 2;
    int slot = blockIdx.x & 3;
    int tok0 = tb*TPC + warp*16;          // this warp's 16 tokens

    // X A-fragments (hi/lo), loaded once: kt0 = dims 0..7, kt1 = dims 8..15
    u32   ahi[8];
    float alo[8];
    {
        const float* x0 = x_in + (tok0 + g    )*DD;
        const float* x8 = x_in + (tok0 + g + 8)*DD;
        float av[8];
        #pragma unroll
        for (int kt = 0; kt < 2; kt++) {
            av[kt*4+0] = x0[kt*8 + tig];
            av[kt*4+1] = x8[kt*8 + tig];
            av[kt*4+2] = x0[kt*8 + tig + 4];
            av[kt*4+3] = x8[kt*8 + tig + 4];
        }
        #pragma unroll
        for (int i = 0; i < 8; i++) {
            ahi[i] = tf32hi(av[i]);
            alo[i] = av[i] - __uint_as_float(ahi[i]);
        }
    }

    float mu[8];                          // C-frags: [0..3]=d 0..7, [4..7]=d 8..15
    #pragma unroll
    for (int i = 0; i < 8; i++) mu[i] = 0.f;
    float sA = 0.f, sB = 0.f;             // row sums: tokens g, g+8

    int vbase   = slot * VPER;
    int tilebeg = vbase >> 3;             // first v-tile of this slot

    // Prologue: prefetch chunk 0 (16KB = 64B/thread) + bias regs
    {
        u32 d0 = (u32)__cvta_generic_to_shared(&buf[0][0]) + tid*16;
        const char* s0 = (const char*)(g_frag + (size_t)tilebeg*512) + tid*16;
        #pragma unroll
        for (int k = 0; k < 4; k++) CPA16(d0 + k*NTHREADS*16, s0 + k*NTHREADS*16);
        CPA_COMMIT();
    }
    float rb = 0.f, rtp = 0.f;
    if (tid < VC) { rb = b[vbase+tid]; rtp = tp[vbase+tid]; }

    for (int ci = 0; ci < NCHUNK; ci++) {
        int cur = ci & 1;
        CPA_WAIT0();
        if (tid < VC) csm[cur][tid] = (rb + t*rtp) * LSCALE;
        __syncthreads();                  // csm ready; prior compute on buf[cur^1] done

        if (ci + 1 < NCHUNK) {
            int tnext = tilebeg + (ci+1)*TPCH;
            u32 d1 = (u32)__cvta_generic_to_shared(&buf[cur^1][0]) + tid*16;
            const char* s1 = (const char*)(g_frag + (size_t)tnext*512) + tid*16;
            #pragma unroll
            for (int k = 0; k < 4; k++) CPA16(d1 + k*NTHREADS*16, s1 + k*NTHREADS*16);
            CPA_COMMIT();
            int c1 = vbase + (ci+1)*VC;
            if (tid < VC) { rb = b[c1+tid]; rtp = tp[c1+tid]; }
        }

        #pragma unroll 2
        for (int tt = 0; tt < TPCH; tt++) {
            const float* sb = buf[cur] + tt*512;
            float4 wh = *(const float4*)(sb +         lane*4);
            float4 wl = *(const float4*)(sb + 128  +  lane*4);
            float4 ch = *(const float4*)(sb + 256  +  lane*4);
            float4 cl = *(const float4*)(sb + 384  +  lane*4);

            // S = (Xhi+Xlo) @ (Whi+Wlo), dropping lo*lo
            float s0 = 0.f, s1v = 0.f, s2 = 0.f, s3 = 0.f;
            MMA(s0,s1v,s2,s3, ahi[0],ahi[1],ahi[2],ahi[3],
                __float_as_uint(wh.x), __float_as_uint(wh.y));
            MMA(s0,s1v,s2,s3, ahi[4],ahi[5],ahi[6],ahi[7],
                __float_as_uint(wh.z), __float_as_uint(wh.w));
            MMA(s0,s1v,s2,s3, __float_as_uint(alo[0]),__float_as_uint(alo[1]),
                __float_as_uint(alo[2]),__float_as_uint(alo[3]),
                __float_as_uint(wh.x), __float_as_uint(wh.y));
            MMA(s0,s1v,s2,s3, __float_as_uint(alo[4]),__float_as_uint(alo[5]),
                __float_as_uint(alo[6]),__float_as_uint(alo[7]),
                __float_as_uint(wh.z), __float_as_uint(wh.w));
            MMA(s0,s1v,s2,s3, ahi[0],ahi[1],ahi[2],ahi[3],
                __float_as_uint(wl.x), __float_as_uint(wl.y));
            MMA(s0,s1v,s2,s3, ahi[4],ahi[5],ahi[6],ahi[7],
                __float_as_uint(wl.z), __float_as_uint(wl.w));

            // p = 2^(S + bias); accumulate row sums
            float2 cb2 = *(const float2*)(&csm[cur][tt*8 + 2*tig]);
            float p0 = ex2f(s0  + cb2.x);
            float p1 = ex2f(s1v + cb2.y);
            float p2 = ex2f(s2  + cb2.x);
            float p3 = ex2f(s3  + cb2.y);
            sA += p0 + p1;
            sB += p2 + p3;

            // Relayout C-frag (cols 2tig,2tig+1) -> A-frag (cols tig, tig+4)
            int base = lane & ~3;
            int src0 = base + (tig >> 1);
            int src2 = src0 + 2;
            float q00 = __shfl_sync(0xffffffffu, p0, src0);
            float q10 = __shfl_sync(0xffffffffu, p1, src0);
            float q02 = __shfl_sync(0xffffffffu, p0, src2);
            float q12 = __shfl_sync(0xffffffffu, p1, src2);
            float q20 = __shfl_sync(0xffffffffu, p2, src0);
            float q30 = __shfl_sync(0xffffffffu, p3, src0);
            float q22 = __shfl_sync(0xffffffffu, p2, src2);
            float q32 = __shfl_sync(0xffffffffu, p3, src2);
            bool odd = (tig & 1);
            float a0f = odd ? q10 : q00;
            float a1f = odd ? q30 : q20;
            float a2f = odd ? q12 : q02;
            float a3f = odd ? q32 : q22;

            u32 ph0 = tf32hi(a0f), ph1 = tf32hi(a1f), ph2 = tf32hi(a2f), ph3 = tf32hi(a3f);
            u32 pl0 = __float_as_uint(a0f - __uint_as_float(ph0));
            u32 pl1 = __float_as_uint(a1f - __uint_as_float(ph1));
            u32 pl2 = __float_as_uint(a2f - __uint_as_float(ph2));
            u32 pl3 = __float_as_uint(a3f - __uint_as_float(ph3));

            // mu += (Phi+Plo) @ CBhi + Phi @ CBlo
            MMA(mu[0],mu[1],mu[2],mu[3], ph0,ph1,ph2,ph3,
                __float_as_uint(ch.x), __float_as_uint(ch.y));
            MMA(mu[4],mu[5],mu[6],mu[7], ph0,ph1,ph2,ph3,
                __float_as_uint(ch.z), __float_as_uint(ch.w));
            MMA(mu[0],mu[1],mu[2],mu[3], pl0,pl1,pl2,pl3,
                __float_as_uint(ch.x), __float_as_uint(ch.y));
            MMA(mu[4],mu[5],mu[6],mu[7], pl0,pl1,pl2,pl3,
                __float_as_uint(ch.z), __float_as_uint(ch.w));
            MMA(mu[0],mu[1],mu[2],mu[3], ph0,ph1,ph2,ph3,
                __float_as_uint(cl.x), __float_as_uint(cl.y));
            MMA(mu[4],mu[5],mu[6],mu[7], ph0,ph1,ph2,ph3,
                __float_as_uint(cl.z), __float_as_uint(cl.w));
        }
    }

    // Row-sum reduce across the 4-thread group (cols)
    sA += __shfl_xor_sync(0xffffffffu, sA, 1);
    sA += __shfl_xor_sync(0xffffffffu, sA, 2);
    sB += __shfl_xor_sync(0xffffffffu, sB, 1);
    sB += __shfl_xor_sync(0xffffffffu, sB, 2);

    // Write per-slot partials: S + 16 mu components per token
    int tokg  = tok0 + g;
    int tokg8 = tokg + 8;
    if (tig == 0) {
        g_part[(slot*17 + 0)*NTOK + tokg ] = sA;
        g_part[(slot*17 + 0)*NTOK + tokg8] = sB;
    }
    {
        int d0 = 2*tig, d1 = 2*tig + 1;
        g_part[(slot*17 + 1 + d0    )*NTOK + tokg ] = mu[0];
        g_part[(slot*17 + 1 + d1    )*NTOK + tokg ] = mu[1];
        g_part[(slot*17 + 1 + d0    )*NTOK + tokg8] = mu[2];
        g_part[(slot*17 + 1 + d1    )*NTOK + tokg8] = mu[3];
        g_part[(slot*17 + 1 + 8 + d0)*NTOK + tokg ] = mu[4];
        g_part[(slot*17 + 1 + 8 + d1)*NTOK + tokg ] = mu[5];
        g_part[(slot*17 + 1 + 8 + d0)*NTOK + tokg8] = mu[6];
        g_part[(slot*17 + 1 + 8 + d1)*NTOK + tokg8] = mu[7];
    }

    // Last CTA of this token block combines all V slots and integrates
    __threadfence();
    __syncthreads();
    if (tid == 0) flag = (atomicAdd(&g_ticket[tb], 1) == VSPLIT - 1);
    __syncthreads();
    if (flag) {
        __threadfence();
        if (tid < TPC) {
            int tok = tb*TPC + tid;
            float S = 0.f, acc[DD];
            #pragma unroll
            for (int d = 0; d < DD; d++) acc[d] = 0.f;
            #pragma unroll
            for (int q = 0; q < VSPLIT; q++) {      // fixed order -> deterministic
                S += __ldcg(&g_part[(q*17 + 0)*NTOK + tok]);
                #pragma unroll
                for (int d = 0; d < DD; d++)
                    acc[d] += __ldcg(&g_part[(q*17 + 1 + d)*NTOK + tok]);
            }
            float invS   = 1.f / S;
            float invden = 1.f / (1.f - t + 1e-10f);
            const float4* xi4 = (const float4*)(x_in + tok*DD);
            const float4* xb4 = (const float4*)(g_x  + tok*DD);
            float4 o[4]; float* of = (float*)o;
            #pragma unroll
            for (int i = 0; i < 4; i++) {
                float4 xi = xi4[i], xbs = xb4[i];
                float xiv[4] = {xi.x, xi.y, xi.z, xi.w};
                float xbv[4] = {xbs.x, xbs.y, xbs.z, xbs.w};
                #pragma unroll
                for (int jj = 0; jj < 4; jj++) {
                    int d = 4*i + jj;
                    of[d] = fmaf(coef, (acc[d]*invS - xiv[jj]) * invden, xbv[jj]);
                }
            }
            float4* xo4 = (float4*)(x_out + tok*DD);
            #pragma unroll
            for (int i = 0; i < 4; i++) xo4[i] = o[i];
        }
        if (tid == 0) g_ticket[tb] = 0;   // reset for next launch / replay
    }
}

// VQ argmin_v ||c_v||^2 - 2 x.c_v
__global__ __launch_bounds__(256)
void quantize_kernel(const float* __restrict__ CB,
                     float* __restrict__ out_x,
                     float* __restrict__ out_idx)
{
    __shared__ __align__(16) float smem[256*DD + 256];
    float* CBsm = smem;
    float* cn2  = smem + 256*DD;

    int tid   = threadIdx.x;
    int tokl  = tid & 63;
    int slice = tid >> 6;
    int tok   = blockIdx.x * 64 + tokl;

    float x[DD];
    {
        const float4* xi4 = (const float4*)(g_x + tok*DD);
        #pragma unroll
        for (int i = 0; i < 4; i++) {
            float4 v4 = xi4[i];
            x[4*i+0]=v4.x; x[4*i+1]=v4.y; x[4*i+2]=v4.z; x[4*i+3]=v4.w;
        }
    }

    float best = 3.4e38f;
    int   bidx = 0;

    for (int c0 = 0; c0 < VV; c0 += 256) {
        __syncthreads();
        {
            const float4* src = (const float4*)(CB + (size_t)c0*DD);
            float4* dst = (float4*)CBsm;
            for (int j = tid; j < 256*DD/4; j += 256) dst[j] = src[j];
        }
        {
            const float* row = CB + (size_t)(c0 + tid)*DD;
            float acc = 0.f;
            #pragma unroll
            for (int d = 0; d < DD; d++) acc = fmaf(row[d], row[d], acc);
            cn2[tid] = acc;
        }
        __syncthreads();

        int vbeg = slice * 64;
        for (int vi = 0; vi < 64; vi++) {
            int v = vbeg + vi;
            const float4* cb4 = (const float4*)(CBsm + v*DD);
            float4 cA=cb4[0], cB4=cb4[1], cC=cb4[2], cD4=cb4[3];
            float a0 = x[0]*cA.x  + x[1]*cA.y  + x[2]*cA.z  + x[3]*cA.w;
            float a1 = x[4]*cB4.x + x[5]*cB4.y + x[6]*cB4.z + x[7]*cB4.w;
            float a2 = x[8]*cC.x  + x[9]*cC.y  + x[10]*cC.z + x[11]*cC.w;
            float a3 = x[12]*cD4.x+ x[13]*cD4.y+ x[14]*cD4.z+ x[15]*cD4.w;
            float dist = cn2[v] - 2.f*((a0+a1) + (a2+a3));
            if (dist < best) { best = dist; bidx = c0 + v; }
        }
    }

    __syncthreads();
    float* redf = smem;
    redf[tid*2] = best;
    ((int*)redf)[tid*2 + 1] = bidx;
    __syncthreads();

    if (slice == 0) {
        float bb = best; int bi = bidx;
        #pragma unroll
        for (int q = 1; q < 4; q++) {
            float dq = redf[(tokl + 64*q)*2];
            int   iq = ((int*)redf)[(tokl + 64*q)*2 + 1];
            if (dq < bb || (dq == bb && iq < bi)) { bb = dq; bi = iq; }
        }
        if (out_idx) out_idx[tok] = (float)bi;
        if (out_x) {
            const float4* xi4 = (const float4*)(g_x + tok*DD);
            float4* o4 = (float4*)(out_x + tok*DD);
            #pragma unroll
            for (int i = 0; i < 4; i++) o4[i] = xi4[i];
        }
    }
}

extern "C" void kernel_launch(void* const* d_in, const int* in_sizes, int n_in,
                              void* d_out, int out_size) {
    const float* x0 = (const float*)d_in[0];
    const float* CB = (const float*)d_in[1];
    const float* W  = (const float*)d_in[2];
    const float* b  = (const float*)d_in[3];
    const float* tp = (const float*)d_in[4];

    copy_kernel<<<(NTOK*DD + 255)/256, 256>>>(x0, NTOK*DD);
    prep_frag<<<(NTILES*32)/256, 256>>>(W, CB);

    const float dt = 1.0f / 7.0f;
    for (int k = 0; k < 7; k++) {
        float t = (float)k / 7.0f;
        velocity_kernel<<<NBLOCKS, NTHREADS>>>(b, tp, t,           0.5f*dt, 0);
        velocity_kernel<<<NBLOCKS, NTHREADS>>>(b, tp, t + 0.5f*dt, dt,      1);
    }

    float* out = (float*)d_out;
    if (out_size >= NTOK*DD + NTOK) {
        quantize_kernel<<<NTOK/64, 256>>>(CB, out, out + NTOK*DD);
    } else if (out_size == NTOK*DD) {
        quantize_kernel<<<NTOK/64, 256>>>(CB, out, nullptr);
    } else {
        quantize_kernel<<<NTOK/64, 256>>>(CB, nullptr, out);
    }
}

// round 9
// speedup vs baseline: 1.3544x; 1.0207x over previous
#include <cuda_runtime.h>

// Fixed shapes: B=32,S=256 -> NTOK=8192; D=16; V=8192; n_steps=8
#define NTOK 8192
#define DD   16
#define VV   8192
#define VC   64              // v per chunk (8 MMA tiles), double-buffered
#define NTHREADS 256
#define WARPS 8
#define TPC  128             // 8 warps x 16 tokens
#define NTB  (NTOK/TPC)      // 64 token blocks
#define VSPLIT 4
#define VPER (VV/VSPLIT)     // 2048
#define NCHUNK (VPER/VC)     // 32
#define NBLOCKS (NTB*VSPLIT) // 256 CTAs -> 2/SM, one wave
#define TPCH 8               // tiles per chunk
#define NTILES (VV/8)        // 1024 v-tiles

#define INVT  1.25f
#define LOG2E 1.4426950408889634f
#define LSCALE (INVT*LOG2E)

typedef unsigned int u32;

// Scratch (allocation-free rule)
__device__ float g_x [NTOK*DD];
__device__ float g_xm[NTOK*DD];
// Fragment pack: per v-tile: [kind][lane][4] floats, kind: 0=Whi 1=Wlo 2=CBhi 3=CBlo
__device__ float g_frag[NTILES*512];
__device__ float g_part[VSPLIT*17*NTOK];
__device__ int   g_ticket[NTB];

__device__ __forceinline__ float ex2f(float x) {
    float r; asm("ex2.approx.ftz.f32 %0, %1;" : "=f"(r) : "f"(x)); return r;
}
__device__ __forceinline__ u32 tf32hi(float f) {
    u32 r; asm("cvt.rna.tf32.f32 %0, %1;" : "=r"(r) : "f"(f)); return r;
}
// D(+=C) = A(m16k8,tf32) * B(k8n8,tf32), fp32 accum, in-place accumulator
#define MMA(d0,d1,d2,d3,a0,a1,a2,a3,b0,b1) \
    asm("mma.sync.aligned.m16n8k8.row.col.f32.tf32.tf32.f32 " \
        "{%0,%1,%2,%3},{%4,%5,%6,%7},{%8,%9},{%0,%1,%2,%3};" \
        : "+f"(d0),"+f"(d1),"+f"(d2),"+f"(d3) \
        : "r"(a0),"r"(a1),"r"(a2),"r"(a3),"r"(b0),"r"(b1))

#define CPA16(dst,src)  asm volatile("cp.async.cg.shared.global [%0],[%1],16;" :: "r"(dst), "l"(src))
#define CPA_COMMIT()    asm volatile("cp.async.commit_group;" ::: "memory")
#define CPA_WAIT0()     asm volatile("cp.async.wait_group 0;" ::: "memory")

__global__ void copy_kernel(const float* __restrict__ src, int n) {
    int i = blockIdx.x * blockDim.x + threadIdx.x;
    if (i < n) g_x[i] = src[i];
}

// Pre-bake W (scaled, hi/lo) and CB (hi/lo) into exact mma B-fragment layout.
__global__ void prep_frag(const float* __restrict__ W,   // [DD][VV]
                          const float* __restrict__ CB)  // [VV][DD]
{
    int gid  = blockIdx.x * blockDim.x + threadIdx.x;   // NTILES*32 threads
    int tile = gid >> 5;
    int lane = gid & 31;
    if (tile >= NTILES) return;
    int g   = lane >> 2;
    int tig = lane & 3;
    int v0  = tile * 8;
    float* out = g_frag + tile*512 + lane*4;

    // W' = W * LSCALE ; B-frag k rows: kt0:{tig,tig+4}, kt1:{tig+8,tig+12}; col v0+g
    int ks[4] = {tig, tig+4, tig+8, tig+12};
    #pragma unroll
    for (int j = 0; j < 4; j++) {
        float wv = W[ks[j]*VV + (v0+g)] * LSCALE;
        u32 hb = tf32hi(wv);
        float hf = __uint_as_float(hb);
        out[      j] = hf;        // kind 0: Whi
        out[128 + j] = wv - hf;   // kind 1: Wlo
    }
    // CB B-frag: k rows v0+tig / v0+tig+4; cols d=g (nt0), d=8+g (nt1)
    int vr0 = v0 + tig, vr1 = v0 + tig + 4;
    float cv[4] = { CB[vr0*DD + g],     CB[vr1*DD + g],
                    CB[vr0*DD + 8 + g], CB[vr1*DD + 8 + g] };
    #pragma unroll
    for (int j = 0; j < 4; j++) {
        u32 hb = tf32hi(cv[j]);
        float hf = __uint_as_float(hb);
        out[256 + j] = hf;        // kind 2: CBhi
        out[384 + j] = cv[j] - hf;// kind 3: CBlo
    }
}

// velocity = (softmax((x@W + b + t*tp)/T) @ CB - x)/(1-t+eps); x_out = g_x + coef*v
// tf32 MMA, hi/lo split everywhere. S uses two parallel 3-deep MMA chains
// (per k-step); mu uses ping-pong accumulators (even/odd tiles) to break the
// kernel-long accumulation RAW chain.
__global__ __launch_bounds__(NTHREADS, 2)
void velocity_kernel(const float* __restrict__ b,
                     const float* __restrict__ tp,
                     float t, float coef, int mode)
{
    __shared__ __align__(16) float buf[2][TPCH*512];   // 2 x 16KB frag chunks
    __shared__ float csm[2][VC];
    __shared__ int flag;

    const float* x_in  = mode ? g_xm : g_x;
    float*       x_out = mode ? g_x  : g_xm;

    int tid  = threadIdx.x;
    int lane = tid & 31;
    int warp = tid >> 5;
    int g    = lane >> 2;
    int tig  = lane & 3;
    int tb   = blockIdx.x >> 2;
    int slot = blockIdx.x & 3;
    int tok0 = tb*TPC + warp*16;          // this warp's 16 tokens

    // X A-fragments (hi/lo), loaded once: kt0 = dims 0..7, kt1 = dims 8..15
    u32   ahi[8];
    float alo[8];
    {
        const float* x0 = x_in + (tok0 + g    )*DD;
        const float* x8 = x_in + (tok0 + g + 8)*DD;
        float av[8];
        #pragma unroll
        for (int kt = 0; kt < 2; kt++) {
            av[kt*4+0] = x0[kt*8 + tig];
            av[kt*4+1] = x8[kt*8 + tig];
            av[kt*4+2] = x0[kt*8 + tig + 4];
            av[kt*4+3] = x8[kt*8 + tig + 4];
        }
        #pragma unroll
        for (int i = 0; i < 8; i++) {
            ahi[i] = tf32hi(av[i]);
            alo[i] = av[i] - __uint_as_float(ahi[i]);
        }
    }

    float muE[8], muO[8];                 // ping-pong C-frags (even/odd tiles)
    #pragma unroll
    for (int i = 0; i < 8; i++) { muE[i] = 0.f; muO[i] = 0.f; }
    float sA = 0.f, sB = 0.f;             // row sums: tokens g, g+8

    int vbase   = slot * VPER;
    int tilebeg = vbase >> 3;             // first v-tile of this slot

    // Prologue: prefetch chunk 0 (16KB = 64B/thread) + bias regs
    {
        u32 d0 = (u32)__cvta_generic_to_shared(&buf[0][0]) + tid*16;
        const char* s0 = (const char*)(g_frag + (size_t)tilebeg*512) + tid*16;
        #pragma unroll
        for (int k = 0; k < 4; k++) CPA16(d0 + k*NTHREADS*16, s0 + k*NTHREADS*16);
        CPA_COMMIT();
    }
    float rb = 0.f, rtp = 0.f;
    if (tid < VC) { rb = b[vbase+tid]; rtp = tp[vbase+tid]; }

    for (int ci = 0; ci < NCHUNK; ci++) {
        int cur = ci & 1;
        CPA_WAIT0();
        if (tid < VC) csm[cur][tid] = (rb + t*rtp) * LSCALE;
        __syncthreads();                  // csm ready; prior compute on buf[cur^1] done

        if (ci + 1 < NCHUNK) {
            int tnext = tilebeg + (ci+1)*TPCH;
            u32 d1 = (u32)__cvta_generic_to_shared(&buf[cur^1][0]) + tid*16;
            const char* s1 = (const char*)(g_frag + (size_t)tnext*512) + tid*16;
            #pragma unroll
            for (int k = 0; k < 4; k++) CPA16(d1 + k*NTHREADS*16, s1 + k*NTHREADS*16);
            CPA_COMMIT();
            int c1 = vbase + (ci+1)*VC;
            if (tid < VC) { rb = b[c1+tid]; rtp = tp[c1+tid]; }
        }

        #pragma unroll
        for (int tt = 0; tt < TPCH; tt++) {
            const float* sb = buf[cur] + tt*512;
            float4 wh = *(const float4*)(sb +         lane*4);
            float4 wl = *(const float4*)(sb + 128  +  lane*4);
            float4 ch = *(const float4*)(sb + 256  +  lane*4);
            float4 cl = *(const float4*)(sb + 384  +  lane*4);
            float* mu = (tt & 1) ? muO : muE;     // ping-pong accumulator

            // S = (Xhi+Xlo)@(Whi+Wlo) minus lo*lo, as TWO parallel chains:
            // chain A = all k-step-0 products, chain B = all k-step-1 products.
            float a0 = 0.f, a1 = 0.f, a2 = 0.f, a3 = 0.f;   // k-step 0
            float b0 = 0.f, b1 = 0.f, b2 = 0.f, b3 = 0.f;   // k-step 1
            MMA(a0,a1,a2,a3, ahi[0],ahi[1],ahi[2],ahi[3],
                __float_as_uint(wh.x), __float_as_uint(wh.y));
            MMA(b0,b1,b2,b3, ahi[4],ahi[5],ahi[6],ahi[7],
                __float_as_uint(wh.z), __float_as_uint(wh.w));
            MMA(a0,a1,a2,a3, __float_as_uint(alo[0]),__float_as_uint(alo[1]),
                __float_as_uint(alo[2]),__float_as_uint(alo[3]),
                __float_as_uint(wh.x), __float_as_uint(wh.y));
            MMA(b0,b1,b2,b3, __float_as_uint(alo[4]),__float_as_uint(alo[5]),
                __float_as_uint(alo[6]),__float_as_uint(alo[7]),
                __float_as_uint(wh.z), __float_as_uint(wh.w));
            MMA(a0,a1,a2,a3, ahi[0],ahi[1],ahi[2],ahi[3],
                __float_as_uint(wl.x), __float_as_uint(wl.y));
            MMA(b0,b1,b2,b3, ahi[4],ahi[5],ahi[6],ahi[7],
                __float_as_uint(wl.z), __float_as_uint(wl.w));

            // p = 2^(S + bias); accumulate row sums
            float2 cb2 = *(const float2*)(&csm[cur][tt*8 + 2*tig]);
            float p0 = ex2f((a0 + b0) + cb2.x);
            float p1 = ex2f((a1 + b1) + cb2.y);
            float p2 = ex2f((a2 + b2) + cb2.x);
            float p3 = ex2f((a3 + b3) + cb2.y);
            sA += p0 + p1;
            sB += p2 + p3;

            // Relayout C-frag (cols 2tig,2tig+1) -> A-frag (cols tig, tig+4)
            int base = lane & ~3;
            int src0 = base + (tig >> 1);
            int src2 = src0 + 2;
            float q00 = __shfl_sync(0xffffffffu, p0, src0);
            float q10 = __shfl_sync(0xffffffffu, p1, src0);
            float q02 = __shfl_sync(0xffffffffu, p0, src2);
            float q12 = __shfl_sync(0xffffffffu, p1, src2);
            float q20 = __shfl_sync(0xffffffffu, p2, src0);
            float q30 = __shfl_sync(0xffffffffu, p3, src0);
            float q22 = __shfl_sync(0xffffffffu, p2, src2);
            float q32 = __shfl_sync(0xffffffffu, p3, src2);
            bool odd = (tig & 1);
            float a0f = odd ? q10 : q00;
            float a1f = odd ? q30 : q20;
            float a2f = odd ? q12 : q02;
            float a3f = odd ? q32 : q22;

            u32 ph0 = tf32hi(a0f), ph1 = tf32hi(a1f), ph2 = tf32hi(a2f), ph3 = tf32hi(a3f);
            u32 pl0 = __float_as_uint(a0f - __uint_as_float(ph0));
            u32 pl1 = __float_as_uint(a1f - __uint_as_float(ph1));
            u32 pl2 = __float_as_uint(a2f - __uint_as_float(ph2));
            u32 pl3 = __float_as_uint(a3f - __uint_as_float(ph3));

            // mu += (Phi+Plo) @ CBhi + Phi @ CBlo  (3-deep per n-half, per set)
            MMA(mu[0],mu[1],mu[2],mu[3], ph0,ph1,ph2,ph3,
                __float_as_uint(ch.x), __float_as_uint(ch.y));
            MMA(mu[4],mu[5],mu[6],mu[7], ph0,ph1,ph2,ph3,
                __float_as_uint(ch.z), __float_as_uint(ch.w));
            MMA(mu[0],mu[1],mu[2],mu[3], pl0,pl1,pl2,pl3,
                __float_as_uint(ch.x), __float_as_uint(ch.y));
            MMA(mu[4],mu[5],mu[6],mu[7], pl0,pl1,pl2,pl3,
                __float_as_uint(ch.z), __float_as_uint(ch.w));
            MMA(mu[0],mu[1],mu[2],mu[3], ph0,ph1,ph2,ph3,
                __float_as_uint(cl.x), __float_as_uint(cl.y));
            MMA(mu[4],mu[5],mu[6],mu[7], ph0,ph1,ph2,ph3,
                __float_as_uint(cl.z), __float_as_uint(cl.w));
        }
    }

    // Merge ping-pong sets
    float mu[8];
    #pragma unroll
    for (int i = 0; i < 8; i++) mu[i] = muE[i] + muO[i];

    // Row-sum reduce across the 4-thread group (cols)
    sA += __shfl_xor_sync(0xffffffffu, sA, 1);
    sA += __shfl_xor_sync(0xffffffffu, sA, 2);
    sB += __shfl_xor_sync(0xffffffffu, sB, 1);
    sB += __shfl_xor_sync(0xffffffffu, sB, 2);

    // Write per-slot partials: S + 16 mu components per token
    int tokg  = tok0 + g;
    int tokg8 = tokg + 8;
    if (tig == 0) {
        g_part[(slot*17 + 0)*NTOK + tokg ] = sA;
        g_part[(slot*17 + 0)*NTOK + tokg8] = sB;
    }
    {
        int d0 = 2*tig, d1 = 2*tig + 1;
        g_part[(slot*17 + 1 + d0    )*NTOK + tokg ] = mu[0];
        g_part[(slot*17 + 1 + d1    )*NTOK + tokg ] = mu[1];
        g_part[(slot*17 + 1 + d0    )*NTOK + tokg8] = mu[2];
        g_part[(slot*17 + 1 + d1    )*NTOK + tokg8] = mu[3];
        g_part[(slot*17 + 1 + 8 + d0)*NTOK + tokg ] = mu[4];
        g_part[(slot*17 + 1 + 8 + d1)*NTOK + tokg ] = mu[5];
        g_part[(slot*17 + 1 + 8 + d0)*NTOK + tokg8] = mu[6];
        g_part[(slot*17 + 1 + 8 + d1)*NTOK + tokg8] = mu[7];
    }

    // Last CTA of this token block combines all V slots and integrates
    __threadfence();
    __syncthreads();
    if (tid == 0) flag = (atomicAdd(&g_ticket[tb], 1) == VSPLIT - 1);
    __syncthreads();
    if (flag) {
        __threadfence();
        if (tid < TPC) {
            int tok = tb*TPC + tid;
            float S = 0.f, acc[DD];
            #pragma unroll
            for (int d = 0; d < DD; d++) acc[d] = 0.f;
            #pragma unroll
            for (int q = 0; q < VSPLIT; q++) {      // fixed order -> deterministic
                S += __ldcg(&g_part[(q*17 + 0)*NTOK + tok]);
                #pragma unroll
                for (int d = 0; d < DD; d++)
                    acc[d] += __ldcg(&g_part[(q*17 + 1 + d)*NTOK + tok]);
            }
            float invS   = 1.f / S;
            float invden = 1.f / (1.f - t + 1e-10f);
            const float4* xi4 = (const float4*)(x_in + tok*DD);
            const float4* xb4 = (const float4*)(g_x  + tok*DD);
            float4 o[4]; float* of = (float*)o;
            #pragma unroll
            for (int i = 0; i < 4; i++) {
                float4 xi = xi4[i], xbs = xb4[i];
                float xiv[4] = {xi.x, xi.y, xi.z, xi.w};
                float xbv[4] = {xbs.x, xbs.y, xbs.z, xbs.w};
                #pragma unroll
                for (int jj = 0; jj < 4; jj++) {
                    int d = 4*i + jj;
                    of[d] = fmaf(coef, (acc[d]*invS - xiv[jj]) * invden, xbv[jj]);
                }
            }
            float4* xo4 = (float4*)(x_out + tok*DD);
            #pragma unroll
            for (int i = 0; i < 4; i++) xo4[i] = o[i];
        }
        if (tid == 0) g_ticket[tb] = 0;   // reset for next launch / replay
    }
}

// VQ argmin_v ||c_v||^2 - 2 x.c_v
__global__ __launch_bounds__(256)
void quantize_kernel(const float* __restrict__ CB,
                     float* __restrict__ out_x,
                     float* __restrict__ out_idx)
{
    __shared__ __align__(16) float smem[256*DD + 256];
    float* CBsm = smem;
    float* cn2  = smem + 256*DD;

    int tid   = threadIdx.x;
    int tokl  = tid & 63;
    int slice = tid >> 6;
    int tok   = blockIdx.x * 64 + tokl;

    float x[DD];
    {
        const float4* xi4 = (const float4*)(g_x + tok*DD);
        #pragma unroll
        for (int i = 0; i < 4; i++) {
            float4 v4 = xi4[i];
            x[4*i+0]=v4.x; x[4*i+1]=v4.y; x[4*i+2]=v4.z; x[4*i+3]=v4.w;
        }
    }

    float best = 3.4e38f;
    int   bidx = 0;

    for (int c0 = 0; c0 < VV; c0 += 256) {
        __syncthreads();
        {
            const float4* src = (const float4*)(CB + (size_t)c0*DD);
            float4* dst = (float4*)CBsm;
            for (int j = tid; j < 256*DD/4; j += 256) dst[j] = src[j];
        }
        {
            const float* row = CB + (size_t)(c0 + tid)*DD;
            float acc = 0.f;
            #pragma unroll
            for (int d = 0; d < DD; d++) acc = fmaf(row[d], row[d], acc);
            cn2[tid] = acc;
        }
        __syncthreads();

        int vbeg = slice * 64;
        for (int vi = 0; vi < 64; vi++) {
            int v = vbeg + vi;
            const float4* cb4 = (const float4*)(CBsm + v*DD);
            float4 cA=cb4[0], cB4=cb4[1], cC=cb4[2], cD4=cb4[3];
            float a0 = x[0]*cA.x  + x[1]*cA.y  + x[2]*cA.z  + x[3]*cA.w;
            float a1 = x[4]*cB4.x + x[5]*cB4.y + x[6]*cB4.z + x[7]*cB4.w;
            float a2 = x[8]*cC.x  + x[9]*cC.y  + x[10]*cC.z + x[11]*cC.w;
            float a3 = x[12]*cD4.x+ x[13]*cD4.y+ x[14]*cD4.z+ x[15]*cD4.w;
            float dist = cn2[v] - 2.f*((a0+a1) + (a2+a3));
            if (dist < best) { best = dist; bidx = c0 + v; }
        }
    }

    __syncthreads();
    float* redf = smem;
    redf[tid*2] = best;
    ((int*)redf)[tid*2 + 1] = bidx;
    __syncthreads();

    if (slice == 0) {
        float bb = best; int bi = bidx;
        #pragma unroll
        for (int q = 1; q < 4; q++) {
            float dq = redf[(tokl + 64*q)*2];
            int   iq = ((int*)redf)[(tokl + 64*q)*2 + 1];
            if (dq < bb || (dq == bb && iq < bi)) { bb = dq; bi = iq; }
        }
        if (out_idx) out_idx[tok] = (float)bi;
        if (out_x) {
            const float4* xi4 = (const float4*)(g_x + tok*DD);
            float4* o4 = (float4*)(out_x + tok*DD);
            #pragma unroll
            for (int i = 0; i < 4; i++) o4[i] = xi4[i];
        }
    }
}

extern "C" void kernel_launch(void* const* d_in, const int* in_sizes, int n_in,
                              void* d_out, int out_size) {
    const float* x0 = (const float*)d_in[0];
    const float* CB = (const float*)d_in[1];
    const float* W  = (const float*)d_in[2];
    const float* b  = (const float*)d_in[3];
    const float* tp = (const float*)d_in[4];

    copy_kernel<<<(NTOK*DD + 255)/256, 256>>>(x0, NTOK*DD);
    prep_frag<<<(NTILES*32)/256, 256>>>(W, CB);

    const float dt = 1.0f / 7.0f;
    for (int k = 0; k < 7; k++) {
        float t = (float)k / 7.0f;
        velocity_kernel<<<NBLOCKS, NTHREADS>>>(b, tp, t,           0.5f*dt, 0);
        velocity_kernel<<<NBLOCKS, NTHREADS>>>(b, tp, t + 0.5f*dt, dt,      1);
    }

    float* out = (float*)d_out;
    if (out_size >= NTOK*DD + NTOK) {
        quantize_kernel<<<NTOK/64, 256>>>(CB, out, out + NTOK*DD);
    } else if (out_size == NTOK*DD) {
        quantize_kernel<<<NTOK/64, 256>>>(CB, out, nullptr);
    } else {
        quantize_kernel<<<NTOK/64, 256>>>(CB, nullptr, out);
    }
}

// round 10
// speedup vs baseline: 1.4787x; 1.0918x over previous
#include <cuda_runtime.h>

// Fixed shapes: B=32,S=256 -> NTOK=8192; D=16; V=8192; n_steps=8
#define NTOK 8192
#define DD   16
#define VV   8192
#define VC   64              // v per chunk (8 MMA tiles), double-buffered
#define NTHREADS 256
#define WARPS 8
#define TPC  128             // 8 warps x 16 tokens
#define NTB  (NTOK/TPC)      // 64 token blocks
#define VSPLIT 4
#define VPER (VV/VSPLIT)     // 2048
#define NCHUNK (VPER/VC)     // 32
#define NBLOCKS (NTB*VSPLIT) // 256 CTAs
#define TPCH 8               // tiles per chunk
#define NTILES (VV/8)        // 1024 v-tiles

#define INVT  1.25f
#define LOG2E 1.4426950408889634f
#define LSCALE (INVT*LOG2E)

// v-tile column permutation: tile position c holds v = PI(c) so that the
// S-GEMM C-fragment IS the mu-GEMM A-fragment (no shfl relayout needed).
// PI = [0,4,1,5,2,6,3,7]
#define PI(c) (((c) & 1) ? (((c) >> 1) + 4) : ((c) >> 1))

typedef unsigned int u32;

// Scratch (allocation-free rule)
__device__ float g_x [NTOK*DD];
__device__ float g_xm[NTOK*DD];
// Fragment pack: per v-tile: [kind][lane][4] floats, kind: 0=Whi 1=Wlo 2=CBhi 3=CBlo
__device__ float g_frag[NTILES*512];
__device__ float g_part[VSPLIT*17*NTOK];
__device__ int   g_ticket[NTB];

__device__ __forceinline__ float ex2f(float x) {
    float r; asm("ex2.approx.ftz.f32 %0, %1;" : "=f"(r) : "f"(x)); return r;
}
__device__ __forceinline__ u32 tf32hi(float f) {
    u32 r; asm("cvt.rna.tf32.f32 %0, %1;" : "=r"(r) : "f"(f)); return r;
}
// D(+=C) = A(m16k8,tf32) * B(k8n8,tf32), fp32 accum, in-place accumulator
#define MMA(d0,d1,d2,d3,a0,a1,a2,a3,b0,b1) \
    asm("mma.sync.aligned.m16n8k8.row.col.f32.tf32.tf32.f32 " \
        "{%0,%1,%2,%3},{%4,%5,%6,%7},{%8,%9},{%0,%1,%2,%3};" \
        : "+f"(d0),"+f"(d1),"+f"(d2),"+f"(d3) \
        : "r"(a0),"r"(a1),"r"(a2),"r"(a3),"r"(b0),"r"(b1))

#define CPA16(dst,src)  asm volatile("cp.async.cg.shared.global [%0],[%1],16;" :: "r"(dst), "l"(src))
#define CPA_COMMIT()    asm volatile("cp.async.commit_group;" ::: "memory")
#define CPA_WAIT0()     asm volatile("cp.async.wait_group 0;" ::: "memory")

__global__ void copy_kernel(const float* __restrict__ src, int n) {
    int i = blockIdx.x * blockDim.x + threadIdx.x;
    if (i < n) g_x[i] = src[i];
}

// Pre-bake W (scaled, hi/lo, PI-permuted columns) and CB (hi/lo) into exact
// mma B-fragment layout.
__global__ void prep_frag(const float* __restrict__ W,   // [DD][VV]
                          const float* __restrict__ CB)  // [VV][DD]
{
    int gid  = blockIdx.x * blockDim.x + threadIdx.x;   // NTILES*32 threads
    int tile = gid >> 5;
    int lane = gid & 31;
    if (tile >= NTILES) return;
    int g   = lane >> 2;        // B-frag n index = tile column position c
    int tig = lane & 3;
    int v0  = tile * 8;
    float* out = g_frag + tile*512 + lane*4;

    // W' = W * LSCALE, column position g holds v0 + PI(g)
    int vw = v0 + PI(g);
    int ks[4] = {tig, tig+4, tig+8, tig+12};
    #pragma unroll
    for (int j = 0; j < 4; j++) {
        float wv = W[ks[j]*VV + vw] * LSCALE;
        u32 hb = tf32hi(wv);
        float hf = __uint_as_float(hb);
        out[      j] = hf;        // kind 0: Whi
        out[128 + j] = wv - hf;   // kind 1: Wlo
    }
    // CB B-frag (natural v order): k rows v0+tig / v0+tig+4; cols d=g, d=8+g
    int vr0 = v0 + tig, vr1 = v0 + tig + 4;
    float cv[4] = { CB[vr0*DD + g],     CB[vr1*DD + g],
                    CB[vr0*DD + 8 + g], CB[vr1*DD + 8 + g] };
    #pragma unroll
    for (int j = 0; j < 4; j++) {
        u32 hb = tf32hi(cv[j]);
        float hf = __uint_as_float(hb);
        out[256 + j] = hf;        // kind 2: CBhi
        out[384 + j] = cv[j] - hf;// kind 3: CBlo
    }
}

// velocity = (softmax((x@W + b + t*tp)/T) @ CB - x)/(1-t+eps); x_out = g_x + coef*v
// tf32 MMA, hi/lo split. PI-permuted W columns make the S C-fragment directly
// usable as the mu A-fragment (zero-shfl P handoff).
__global__ __launch_bounds__(NTHREADS, 2)
void velocity_kernel(const float* __restrict__ b,
                     const float* __restrict__ tp,
                     float t, float coef, int mode)
{
    __shared__ __align__(16) float buf[2][TPCH*512];   // 2 x 16KB frag chunks
    __shared__ float csm[2][VC];
    __shared__ int flag;

    const float* x_in  = mode ? g_xm : g_x;
    float*       x_out = mode ? g_x  : g_xm;

    int tid  = threadIdx.x;
    int lane = tid & 31;
    int warp = tid >> 5;
    int g    = lane >> 2;
    int tig  = lane & 3;
    int tb   = blockIdx.x >> 2;
    int slot = blockIdx.x & 3;
    int tok0 = tb*TPC + warp*16;          // this warp's 16 tokens

    // bias gather index (PI-permuted within each 8-tile)
    int bperm = (tid & ~7) + PI(tid & 7); // valid for tid < VC

    // X A-fragments (hi/lo), loaded once: kt0 = dims 0..7, kt1 = dims 8..15
    u32   ahi[8];
    float alo[8];
    {
        const float* x0 = x_in + (tok0 + g    )*DD;
        const float* x8 = x_in + (tok0 + g + 8)*DD;
        float av[8];
        #pragma unroll
        for (int kt = 0; kt < 2; kt++) {
            av[kt*4+0] = x0[kt*8 + tig];
            av[kt*4+1] = x8[kt*8 + tig];
            av[kt*4+2] = x0[kt*8 + tig + 4];
            av[kt*4+3] = x8[kt*8 + tig + 4];
        }
        #pragma unroll
        for (int i = 0; i < 8; i++) {
            ahi[i] = tf32hi(av[i]);
            alo[i] = av[i] - __uint_as_float(ahi[i]);
        }
    }

    float muE[8], muO[8];                 // ping-pong C-frags (even/odd tiles)
    #pragma unroll
    for (int i = 0; i < 8; i++) { muE[i] = 0.f; muO[i] = 0.f; }
    float sA = 0.f, sB = 0.f;             // row sums: tokens g, g+8

    int vbase   = slot * VPER;
    int tilebeg = vbase >> 3;             // first v-tile of this slot

    // Prologue: prefetch chunk 0 (16KB = 64B/thread) + bias regs
    {
        u32 d0 = (u32)__cvta_generic_to_shared(&buf[0][0]) + tid*16;
        const char* s0 = (const char*)(g_frag + (size_t)tilebeg*512) + tid*16;
        #pragma unroll
        for (int k = 0; k < 4; k++) CPA16(d0 + k*NTHREADS*16, s0 + k*NTHREADS*16);
        CPA_COMMIT();
    }
    float rb = 0.f, rtp = 0.f;
    if (tid < VC) { rb = b[vbase+bperm]; rtp = tp[vbase+bperm]; }

    for (int ci = 0; ci < NCHUNK; ci++) {
        int cur = ci & 1;
        CPA_WAIT0();
        if (tid < VC) csm[cur][tid] = (rb + t*rtp) * LSCALE;
        __syncthreads();                  // csm ready; prior compute on buf[cur^1] done

        if (ci + 1 < NCHUNK) {
            int tnext = tilebeg + (ci+1)*TPCH;
            u32 d1 = (u32)__cvta_generic_to_shared(&buf[cur^1][0]) + tid*16;
            const char* s1 = (const char*)(g_frag + (size_t)tnext*512) + tid*16;
            #pragma unroll
            for (int k = 0; k < 4; k++) CPA16(d1 + k*NTHREADS*16, s1 + k*NTHREADS*16);
            CPA_COMMIT();
            int c1 = vbase + (ci+1)*VC;
            if (tid < VC) { rb = b[c1+bperm]; rtp = tp[c1+bperm]; }
        }

        #pragma unroll
        for (int tt = 0; tt < TPCH; tt++) {
            const float* sb = buf[cur] + tt*512;
            float4 wh = *(const float4*)(sb +         lane*4);
            float4 wl = *(const float4*)(sb + 128  +  lane*4);
            float4 ch = *(const float4*)(sb + 256  +  lane*4);
            float4 cl = *(const float4*)(sb + 384  +  lane*4);
            float* mu = (tt & 1) ? muO : muE;     // ping-pong accumulator

            // S = (Xhi+Xlo)@(Whi+Wlo) minus lo*lo, two parallel chains by k-step
            float a0 = 0.f, a1 = 0.f, a2 = 0.f, a3 = 0.f;   // k-step 0
            float b0 = 0.f, b1 = 0.f, b2 = 0.f, b3 = 0.f;   // k-step 1
            MMA(a0,a1,a2,a3, ahi[0],ahi[1],ahi[2],ahi[3],
                __float_as_uint(wh.x), __float_as_uint(wh.y));
            MMA(b0,b1,b2,b3, ahi[4],ahi[5],ahi[6],ahi[7],
                __float_as_uint(wh.z), __float_as_uint(wh.w));
            MMA(a0,a1,a2,a3, __float_as_uint(alo[0]),__float_as_uint(alo[1]),
                __float_as_uint(alo[2]),__float_as_uint(alo[3]),
                __float_as_uint(wh.x), __float_as_uint(wh.y));
            MMA(b0,b1,b2,b3, __float_as_uint(alo[4]),__float_as_uint(alo[5]),
                __float_as_uint(alo[6]),__float_as_uint(alo[7]),
                __float_as_uint(wh.z), __float_as_uint(wh.w));
            MMA(a0,a1,a2,a3, ahi[0],ahi[1],ahi[2],ahi[3],
                __float_as_uint(wl.x), __float_as_uint(wl.y));
            MMA(b0,b1,b2,b3, ahi[4],ahi[5],ahi[6],ahi[7],
                __float_as_uint(wl.z), __float_as_uint(wl.w));

            // p = 2^(S + bias); C-frag slots: p0=C[g][2tig] p1=C[g][2tig+1]
            //                                 p2=C[g+8][2tig] p3=C[g+8][2tig+1]
            float2 cb2 = *(const float2*)(&csm[cur][tt*8 + 2*tig]);
            float p0 = ex2f((a0 + b0) + cb2.x);
            float p1 = ex2f((a1 + b1) + cb2.y);
            float p2 = ex2f((a2 + b2) + cb2.x);
            float p3 = ex2f((a3 + b3) + cb2.y);
            sA += p0 + p1;
            sB += p2 + p3;

            // PI-permutation makes held C-frag == needed A-frag:
            // A = {P[g][tig], P[g+8][tig], P[g][tig+4], P[g+8][tig+4]}
            //   = {p0, p2, p1, p3}  -- pure register renaming, no shfl.
            u32 ph0 = tf32hi(p0), ph1 = tf32hi(p2), ph2 = tf32hi(p1), ph3 = tf32hi(p3);
            u32 pl0 = __float_as_uint(p0 - __uint_as_float(ph0));
            u32 pl1 = __float_as_uint(p2 - __uint_as_float(ph1));
            u32 pl2 = __float_as_uint(p1 - __uint_as_float(ph2));
            u32 pl3 = __float_as_uint(p3 - __uint_as_float(ph3));

            // mu += (Phi+Plo) @ CBhi + Phi @ CBlo
            MMA(mu[0],mu[1],mu[2],mu[3], ph0,ph1,ph2,ph3,
                __float_as_uint(ch.x), __float_as_uint(ch.y));
            MMA(mu[4],mu[5],mu[6],mu[7], ph0,ph1,ph2,ph3,
                __float_as_uint(ch.z), __float_as_uint(ch.w));
            MMA(mu[0],mu[1],mu[2],mu[3], pl0,pl1,pl2,pl3,
                __float_as_uint(ch.x), __float_as_uint(ch.y));
            MMA(mu[4],mu[5],mu[6],mu[7], pl0,pl1,pl2,pl3,
                __float_as_uint(ch.z), __float_as_uint(ch.w));
            MMA(mu[0],mu[1],mu[2],mu[3], ph0,ph1,ph2,ph3,
                __float_as_uint(cl.x), __float_as_uint(cl.y));
            MMA(mu[4],mu[5],mu[6],mu[7], ph0,ph1,ph2,ph3,
                __float_as_uint(cl.z), __float_as_uint(cl.w));
        }
    }

    // Merge ping-pong sets
    float mu[8];
    #pragma unroll
    for (int i = 0; i < 8; i++) mu[i] = muE[i] + muO[i];

    // Row-sum reduce across the 4-thread group (cols)
    sA += __shfl_xor_sync(0xffffffffu, sA, 1);
    sA += __shfl_xor_sync(0xffffffffu, sA, 2);
    sB += __shfl_xor_sync(0xffffffffu, sB, 1);
    sB += __shfl_xor_sync(0xffffffffu, sB, 2);

    // Write per-slot partials: S + 16 mu components per token
    int tokg  = tok0 + g;
    int tokg8 = tokg + 8;
    if (tig == 0) {
        g_part[(slot*17 + 0)*NTOK + tokg ] = sA;
        g_part[(slot*17 + 0)*NTOK + tokg8] = sB;
    }
    {
        int d0 = 2*tig, d1 = 2*tig + 1;
        g_part[(slot*17 + 1 + d0    )*NTOK + tokg ] = mu[0];
        g_part[(slot*17 + 1 + d1    )*NTOK + tokg ] = mu[1];
        g_part[(slot*17 + 1 + d0    )*NTOK + tokg8] = mu[2];
        g_part[(slot*17 + 1 + d1    )*NTOK + tokg8] = mu[3];
        g_part[(slot*17 + 1 + 8 + d0)*NTOK + tokg ] = mu[4];
        g_part[(slot*17 + 1 + 8 + d1)*NTOK + tokg ] = mu[5];
        g_part[(slot*17 + 1 + 8 + d0)*NTOK + tokg8] = mu[6];
        g_part[(slot*17 + 1 + 8 + d1)*NTOK + tokg8] = mu[7];
    }

    // Last CTA of this token block combines all V slots and integrates
    __threadfence();
    __syncthreads();
    if (tid == 0) flag = (atomicAdd(&g_ticket[tb], 1) == VSPLIT - 1);
    __syncthreads();
    if (flag) {
        __threadfence();
        if (tid < TPC) {
            int tok = tb*TPC + tid;
            float S = 0.f, acc[DD];
            #pragma unroll
            for (int d = 0; d < DD; d++) acc[d] = 0.f;
            #pragma unroll
            for (int q = 0; q < VSPLIT; q++) {      // fixed order -> deterministic
                S += __ldcg(&g_part[(q*17 + 0)*NTOK + tok]);
                #pragma unroll
                for (int d = 0; d < DD; d++)
                    acc[d] += __ldcg(&g_part[(q*17 + 1 + d)*NTOK + tok]);
            }
            float invS   = 1.f / S;
            float invden = 1.f / (1.f - t + 1e-10f);
            const float4* xi4 = (const float4*)(x_in + tok*DD);
            const float4* xb4 = (const float4*)(g_x  + tok*DD);
            float4 o[4]; float* of = (float*)o;
            #pragma unroll
            for (int i = 0; i < 4; i++) {
                float4 xi = xi4[i], xbs = xb4[i];
                float xiv[4] = {xi.x, xi.y, xi.z, xi.w};
                float xbv[4] = {xbs.x, xbs.y, xbs.z, xbs.w};
                #pragma unroll
                for (int jj = 0; jj < 4; jj++) {
                    int d = 4*i + jj;
                    of[d] = fmaf(coef, (acc[d]*invS - xiv[jj]) * invden, xbv[jj]);
                }
            }
            float4* xo4 = (float4*)(x_out + tok*DD);
            #pragma unroll
            for (int i = 0; i < 4; i++) xo4[i] = o[i];
        }
        if (tid == 0) g_ticket[tb] = 0;   // reset for next launch / replay
    }
}

// VQ argmin_v ||c_v||^2 - 2 x.c_v
__global__ __launch_bounds__(256)
void quantize_kernel(const float* __restrict__ CB,
                     float* __restrict__ out_x,
                     float* __restrict__ out_idx)
{
    __shared__ __align__(16) float smem[256*DD + 256];
    float* CBsm = smem;
    float* cn2  = smem + 256*DD;

    int tid   = threadIdx.x;
    int tokl  = tid & 63;
    int slice = tid >> 6;
    int tok   = blockIdx.x * 64 + tokl;

    float x[DD];
    {
        const float4* xi4 = (const float4*)(g_x + tok*DD);
        #pragma unroll
        for (int i = 0; i < 4; i++) {
            float4 v4 = xi4[i];
            x[4*i+0]=v4.x; x[4*i+1]=v4.y; x[4*i+2]=v4.z; x[4*i+3]=v4.w;
        }
    }

    float best = 3.4e38f;
    int   bidx = 0;

    for (int c0 = 0; c0 < VV; c0 += 256) {
        __syncthreads();
        {
            const float4* src = (const float4*)(CB + (size_t)c0*DD);
            float4* dst = (float4*)CBsm;
            for (int j = tid; j < 256*DD/4; j += 256) dst[j] = src[j];
        }
        {
            const float* row = CB + (size_t)(c0 + tid)*DD;
            float acc = 0.f;
            #pragma unroll
            for (int d = 0; d < DD; d++) acc = fmaf(row[d], row[d], acc);
            cn2[tid] = acc;
        }
        __syncthreads();

        int vbeg = slice * 64;
        for (int vi = 0; vi < 64; vi++) {
            int v = vbeg + vi;
            const float4* cb4 = (const float4*)(CBsm + v*DD);
            float4 cA=cb4[0], cB4=cb4[1], cC=cb4[2], cD4=cb4[3];
            float a0 = x[0]*cA.x  + x[1]*cA.y  + x[2]*cA.z  + x[3]*cA.w;
            float a1 = x[4]*cB4.x + x[5]*cB4.y + x[6]*cB4.z + x[7]*cB4.w;
            float a2 = x[8]*cC.x  + x[9]*cC.y  + x[10]*cC.z + x[11]*cC.w;
            float a3 = x[12]*cD4.x+ x[13]*cD4.y+ x[14]*cD4.z+ x[15]*cD4.w;
            float dist = cn2[v] - 2.f*((a0+a1) + (a2+a3));
            if (dist < best) { best = dist; bidx = c0 + v; }
        }
    }

    __syncthreads();
    float* redf = smem;
    redf[tid*2] = best;
    ((int*)redf)[tid*2 + 1] = bidx;
    __syncthreads();

    if (slice == 0) {
        float bb = best; int bi = bidx;
        #pragma unroll
        for (int q = 1; q < 4; q++) {
            float dq = redf[(tokl + 64*q)*2];
            int   iq = ((int*)redf)[(tokl + 64*q)*2 + 1];
            if (dq < bb || (dq == bb && iq < bi)) { bb = dq; bi = iq; }
        }
        if (out_idx) out_idx[tok] = (float)bi;
        if (out_x) {
            const float4* xi4 = (const float4*)(g_x + tok*DD);
            float4* o4 = (float4*)(out_x + tok*DD);
            #pragma unroll
            for (int i = 0; i < 4; i++) o4[i] = xi4[i];
        }
    }
}

extern "C" void kernel_launch(void* const* d_in, const int* in_sizes, int n_in,
                              void* d_out, int out_size) {
    const float* x0 = (const float*)d_in[0];
    const float* CB = (const float*)d_in[1];
    const float* W  = (const float*)d_in[2];
    const float* b  = (const float*)d_in[3];
    const float* tp = (const float*)d_in[4];

    copy_kernel<<<(NTOK*DD + 255)/256, 256>>>(x0, NTOK*DD);
    prep_frag<<<(NTILES*32)/256, 256>>>(W, CB);

    const float dt = 1.0f / 7.0f;
    for (int k = 0; k < 7; k++) {
        float t = (float)k / 7.0f;
        velocity_kernel<<<NBLOCKS, NTHREADS>>>(b, tp, t,           0.5f*dt, 0);
        velocity_kernel<<<NBLOCKS, NTHREADS>>>(b, tp, t + 0.5f*dt, dt,      1);
    }

    float* out = (float*)d_out;
    if (out_size >= NTOK*DD + NTOK) {
        quantize_kernel<<<NTOK/64, 256>>>(CB, out, out + NTOK*DD);
    } else if (out_size == NTOK*DD) {
        quantize_kernel<<<NTOK/64, 256>>>(CB, out, nullptr);
    } else {
        quantize_kernel<<<NTOK/64, 256>>>(CB, nullptr, out);
    }
}

// round 12
// speedup vs baseline: 2.2340x; 1.5108x over previous
#include <cuda_runtime.h>

// Fixed shapes: B=32,S=256 -> NTOK=8192; D=16; V=8192; n_steps=8
#define NTOK 8192
#define DD   16
#define VV   8192
#define VC   64              // v per chunk = 4 units of 16 v, double-buffered
#define NTHREADS 256
#define WARPS 8
#define TPC  128             // 8 warps x 16 tokens
#define NTB  (NTOK/TPC)      // 64 token blocks
#define VSPLIT 4
#define VPER (VV/VSPLIT)     // 2048
#define NCHUNK (VPER/VC)     // 32
#define NBLOCKS (NTB*VSPLIT) // 256 CTAs
#define UPCH 4               // 2-tile units per chunk
#define NUNITS (VV/16)       // 512

#define INVT  1.25f
#define LOG2E 1.4426950408889634f
#define LSCALE (INVT*LOG2E)

typedef unsigned int u32;

// Scratch (allocation-free rule)
__device__ float g_x [NTOK*DD];
__device__ float g_xm[NTOK*DD];
// Per 16-v unit: 512 u32 (2KB), bf16 fragment pack:
// [0:128)   W tile0: lane*4 + {hi0,hi1,lo0,lo1}
// [128:256) W tile1: same
// [256:384) CB dims 0..7:  lane*4 + {hi0,hi1,lo0,lo1}
// [384:512) CB dims 8..15: same
__device__ u32  g_frag[NUNITS*512];
__device__ float g_part[VSPLIT*17*NTOK];
__device__ int   g_ticket[NTB];

__device__ __forceinline__ float ex2f(float x) {
    float r; asm("ex2.approx.ftz.f32 %0, %1;" : "=f"(r) : "f"(x)); return r;
}
// pack {lo16(b), lo16(a)}: bf16x2 with low half = trunc-bf16(a), high = trunc-bf16(b)
__device__ __forceinline__ u32 prmt_hi(float a, float b) {
    u32 r; asm("prmt.b32 %0, %1, %2, 0x7632;" : "=r"(r)
               : "r"(__float_as_uint(a)), "r"(__float_as_uint(b))); return r;
}
// bf16x2: low = rn(lo), high = rn(hi)
__device__ __forceinline__ u32 cvtb2(float hi, float lo) {
    u32 r; asm("cvt.rn.bf16x2.f32 %0, %1, %2;" : "=r"(r) : "f"(hi), "f"(lo)); return r;
}
__device__ __forceinline__ float trunc16(float a) {
    return __uint_as_float(__float_as_uint(a) & 0xffff0000u);
}
// D(+=D) = A(m16k16,bf16) * B(k16n8,bf16), fp32 accum
#define MMAB(d0,d1,d2,d3,a0,a1,a2,a3,b0,b1) \
    asm("mma.sync.aligned.m16n8k16.row.col.f32.bf16.bf16.f32 " \
        "{%0,%1,%2,%3},{%4,%5,%6,%7},{%8,%9},{%0,%1,%2,%3};" \
        : "+f"(d0),"+f"(d1),"+f"(d2),"+f"(d3) \
        : "r"(a0),"r"(a1),"r"(a2),"r"(a3),"r"(b0),"r"(b1))

#define CPA16(dst,src)  asm volatile("cp.async.cg.shared.global [%0],[%1],16;" :: "r"(dst), "l"(src))
#define CPA_COMMIT()    asm volatile("cp.async.commit_group;" ::: "memory")
#define CPA_WAIT0()     asm volatile("cp.async.wait_group 0;" ::: "memory")

__global__ void copy_kernel(const float* __restrict__ src, int n) {
    int i = blockIdx.x * blockDim.x + threadIdx.x;
    if (i < n) g_x[i] = src[i];
}

// Pre-bake W' = W*LSCALE and CB into bf16 hi/lo m16n8k16 B-fragments.
__global__ void prep_frag(const float* __restrict__ W,   // [DD][VV]
                          const float* __restrict__ CB)  // [VV][DD]
{
    int gid  = blockIdx.x * blockDim.x + threadIdx.x;    // NUNITS*32
    int unit = gid >> 5;
    int lane = gid & 31;
    if (unit >= NUNITS) return;
    int g   = lane >> 2;
    int tig = lane & 3;
    int v0  = unit * 16;
    u32* out = g_frag + unit*512;

    // W tiles: B = W'[k=16 dims][n=8 v], col v = tile base + g
    #pragma unroll
    for (int T = 0; T < 2; T++) {
        int v = v0 + 8*T + g;
        float w0 = W[(2*tig    )*VV + v] * LSCALE;
        float w1 = W[(2*tig + 1)*VV + v] * LSCALE;
        float w2 = W[(2*tig + 8)*VV + v] * LSCALE;
        float w3 = W[(2*tig + 9)*VV + v] * LSCALE;
        out[T*128 + lane*4 + 0] = prmt_hi(w0, w1);
        out[T*128 + lane*4 + 1] = prmt_hi(w2, w3);
        out[T*128 + lane*4 + 2] = cvtb2(w1 - trunc16(w1), w0 - trunc16(w0));
        out[T*128 + lane*4 + 3] = cvtb2(w3 - trunc16(w3), w2 - trunc16(w2));
    }
    // CB halves: B = CB[k=16 v (unit)][n=8 dims], col d = 8h + g
    #pragma unroll
    for (int h = 0; h < 2; h++) {
        int d = 8*h + g;
        float c0 = CB[(v0 + 2*tig    )*DD + d];
        float c1 = CB[(v0 + 2*tig + 1)*DD + d];
        float c2 = CB[(v0 + 2*tig + 8)*DD + d];
        float c3 = CB[(v0 + 2*tig + 9)*DD + d];
        out[256 + h*128 + lane*4 + 0] = prmt_hi(c0, c1);
        out[256 + h*128 + lane*4 + 1] = prmt_hi(c2, c3);
        out[256 + h*128 + lane*4 + 2] = cvtb2(c1 - trunc16(c1), c0 - trunc16(c0));
        out[256 + h*128 + lane*4 + 3] = cvtb2(c3 - trunc16(c3), c2 - trunc16(c2));
    }
}

// velocity = (softmax((x@W + b + t*tp)/T) @ CB - x)/(1-t+eps); x_out = g_x + coef*v
// bf16 m16n8k16, hi/lo split (drop lo*lo). S C-frag feeds mu A-frag directly.
__global__ __launch_bounds__(NTHREADS, 2)
void velocity_kernel(const float* __restrict__ b,
                     const float* __restrict__ tp,
                     float t, float coef, int mode)
{
    __shared__ __align__(16) u32 buf[2][UPCH*512];   // 2 x 8KB frag chunks
    __shared__ float csm[2][VC];
    __shared__ int flag;

    const float* x_in  = mode ? g_xm : g_x;
    float*       x_out = mode ? g_x  : g_xm;

    int tid  = threadIdx.x;
    int lane = tid & 31;
    int warp = tid >> 5;
    int g    = lane >> 2;
    int tig  = lane & 3;
    int tb   = blockIdx.x >> 2;
    int slot = blockIdx.x & 3;
    int tok0 = tb*TPC + warp*16;          // this warp's 16 tokens

    // X A-fragments (bf16 hi/lo), loaded once
    u32 xhi[4], xlo[4];
    {
        const float* x0p = x_in + (tok0 + g    )*DD;
        const float* x8p = x_in + (tok0 + g + 8)*DD;
        float v0 = x0p[2*tig],     v1 = x0p[2*tig + 1];
        float v2 = x8p[2*tig],     v3 = x8p[2*tig + 1];
        float v4 = x0p[2*tig + 8], v5 = x0p[2*tig + 9];
        float v6 = x8p[2*tig + 8], v7 = x8p[2*tig + 9];
        xhi[0] = prmt_hi(v0, v1);  xhi[1] = prmt_hi(v2, v3);
        xhi[2] = prmt_hi(v4, v5);  xhi[3] = prmt_hi(v6, v7);
        xlo[0] = cvtb2(v1 - trunc16(v1), v0 - trunc16(v0));
        xlo[1] = cvtb2(v3 - trunc16(v3), v2 - trunc16(v2));
        xlo[2] = cvtb2(v5 - trunc16(v5), v4 - trunc16(v4));
        xlo[3] = cvtb2(v7 - trunc16(v7), v6 - trunc16(v6));
    }

    float muE[8], muO[8];                 // ping-pong C-frags (even/odd units)
    #pragma unroll
    for (int i = 0; i < 8; i++) { muE[i] = 0.f; muO[i] = 0.f; }
    float sA = 0.f, sB = 0.f;             // row sums: tokens g, g+8

    int vbase   = slot * VPER;
    int unitbeg = vbase >> 4;             // first unit of this slot

    // Prologue: prefetch chunk 0 (8KB = 32B/thread) + bias regs
    {
        u32 d0 = (u32)__cvta_generic_to_shared(&buf[0][0]) + tid*16;
        const char* s0 = (const char*)(g_frag + (size_t)unitbeg*512) + tid*16;
        #pragma unroll
        for (int k = 0; k < 2; k++) CPA16(d0 + k*NTHREADS*16, s0 + k*NTHREADS*16);
        CPA_COMMIT();
    }
    float rb = 0.f, rtp = 0.f;
    if (tid < VC) { rb = b[vbase+tid]; rtp = tp[vbase+tid]; }

    for (int ci = 0; ci < NCHUNK; ci++) {
        int cur = ci & 1;
        CPA_WAIT0();
        if (tid < VC) csm[cur][tid] = (rb + t*rtp) * LSCALE;
        __syncthreads();                  // csm ready; prior compute on buf[cur^1] done

        if (ci + 1 < NCHUNK) {
            int unext = unitbeg + (ci+1)*UPCH;
            u32 d1 = (u32)__cvta_generic_to_shared(&buf[cur^1][0]) + tid*16;
            const char* s1 = (const char*)(g_frag + (size_t)unext*512) + tid*16;
            #pragma unroll
            for (int k = 0; k < 2; k++) CPA16(d1 + k*NTHREADS*16, s1 + k*NTHREADS*16);
            CPA_COMMIT();
            int c1 = vbase + (ci+1)*VC;
            if (tid < VC) { rb = b[c1+tid]; rtp = tp[c1+tid]; }
        }

        const u32*   bufc = buf[cur];
        const float* csmc = csm[cur];
        #pragma unroll
        for (int uu = 0; uu < UPCH; uu++) {
            const u32* ub = bufc + uu*512;
            uint4 wt0 = *(const uint4*)(ub +        lane*4);  // {hi0,hi1,lo0,lo1}
            uint4 wt1 = *(const uint4*)(ub + 128 +  lane*4);
            uint4 cb0 = *(const uint4*)(ub + 256 +  lane*4);  // CB dims 0..7
            uint4 cb1 = *(const uint4*)(ub + 384 +  lane*4);  // CB dims 8..15
            float* mu = (uu & 1) ? muO : muE;

            // S tile0 and tile1 (independent 3-deep chains)
            float s0=0.f, s1=0.f, s2=0.f, s3=0.f;
            float r0=0.f, r1=0.f, r2=0.f, r3=0.f;
            MMAB(s0,s1,s2,s3, xhi[0],xhi[1],xhi[2],xhi[3], wt0.x, wt0.y);
            MMAB(r0,r1,r2,r3, xhi[0],xhi[1],xhi[2],xhi[3], wt1.x, wt1.y);
            MMAB(s0,s1,s2,s3, xlo[0],xlo[1],xlo[2],xlo[3], wt0.x, wt0.y);
            MMAB(r0,r1,r2,r3, xlo[0],xlo[1],xlo[2],xlo[3], wt1.x, wt1.y);
            MMAB(s0,s1,s2,s3, xhi[0],xhi[1],xhi[2],xhi[3], wt0.z, wt0.w);
            MMAB(r0,r1,r2,r3, xhi[0],xhi[1],xhi[2],xhi[3], wt1.z, wt1.w);

            // p = 2^(S + bias)
            int voff = uu*16;
            float2 bb0 = *(const float2*)(csmc + voff +     2*tig);
            float2 bb1 = *(const float2*)(csmc + voff + 8 + 2*tig);
            float p0 = ex2f(s0 + bb0.x), p1 = ex2f(s1 + bb0.y);
            float p2 = ex2f(s2 + bb0.x), p3 = ex2f(s3 + bb0.y);
            float q0 = ex2f(r0 + bb1.x), q1 = ex2f(r1 + bb1.y);
            float q2 = ex2f(r2 + bb1.x), q3 = ex2f(r3 + bb1.y);
            sA += (p0 + p1) + (q0 + q1);
            sB += (p2 + p3) + (q2 + q3);

            // S C-frag == mu A-frag (k16): a0=t0{p0,p1} a1=t0{p2,p3} a2=t1{q0,q1} a3=t1{q2,q3}
            u32 ph0 = prmt_hi(p0, p1), ph1 = prmt_hi(p2, p3);
            u32 ph2 = prmt_hi(q0, q1), ph3 = prmt_hi(q2, q3);
            u32 pl0 = cvtb2(p1 - trunc16(p1), p0 - trunc16(p0));
            u32 pl1 = cvtb2(p3 - trunc16(p3), p2 - trunc16(p2));
            u32 pl2 = cvtb2(q1 - trunc16(q1), q0 - trunc16(q0));
            u32 pl3 = cvtb2(q3 - trunc16(q3), q2 - trunc16(q2));

            // mu += (Phi+Plo) @ CBhi + Phi @ CBlo   (both tiles at once, K=16)
            MMAB(mu[0],mu[1],mu[2],mu[3], ph0,ph1,ph2,ph3, cb0.x, cb0.y);
            MMAB(mu[4],mu[5],mu[6],mu[7], ph0,ph1,ph2,ph3, cb1.x, cb1.y);
            MMAB(mu[0],mu[1],mu[2],mu[3], pl0,pl1,pl2,pl3, cb0.x, cb0.y);
            MMAB(mu[4],mu[5],mu[6],mu[7], pl0,pl1,pl2,pl3, cb1.x, cb1.y);
            MMAB(mu[0],mu[1],mu[2],mu[3], ph0,ph1,ph2,ph3, cb0.z, cb0.w);
            MMAB(mu[4],mu[5],mu[6],mu[7], ph0,ph1,ph2,ph3, cb1.z, cb1.w);
        }
        __syncthreads();                  // done with buf[cur] before it refills
    }

    // Merge ping-pong sets
    float mu[8];
    #pragma unroll
    for (int i = 0; i < 8; i++) mu[i] = muE[i] + muO[i];

    // Row-sum reduce across the 4-thread group (cols)
    sA += __shfl_xor_sync(0xffffffffu, sA, 1);
    sA += __shfl_xor_sync(0xffffffffu, sA, 2);
    sB += __shfl_xor_sync(0xffffffffu, sB, 1);
    sB += __shfl_xor_sync(0xffffffffu, sB, 2);

    // Write per-slot partials: S + 16 mu components per token
    int tokg  = tok0 + g;
    int tokg8 = tokg + 8;
    if (tig == 0) {
        g_part[(slot*17 + 0)*NTOK + tokg ] = sA;
        g_part[(slot*17 + 0)*NTOK + tokg8] = sB;
    }
    {
        int d0 = 2*tig, d1 = 2*tig + 1;
        g_part[(slot*17 + 1 + d0    )*NTOK + tokg ] = mu[0];
        g_part[(slot*17 + 1 + d1    )*NTOK + tokg ] = mu[1];
        g_part[(slot*17 + 1 + d0    )*NTOK + tokg8] = mu[2];
        g_part[(slot*17 + 1 + d1    )*NTOK + tokg8] = mu[3];
        g_part[(slot*17 + 1 + 8 + d0)*NTOK + tokg ] = mu[4];
        g_part[(slot*17 + 1 + 8 + d1)*NTOK + tokg ] = mu[5];
        g_part[(slot*17 + 1 + 8 + d0)*NTOK + tokg8] = mu[6];
        g_part[(slot*17 + 1 + 8 + d1)*NTOK + tokg8] = mu[7];
    }

    // Last CTA of this token block combines all V slots and integrates
    __threadfence();
    __syncthreads();
    if (tid == 0) flag = (atomicAdd(&g_ticket[tb], 1) == VSPLIT - 1);
    __syncthreads();
    if (flag) {
        __threadfence();
        if (tid < TPC) {
            int tok = tb*TPC + tid;
            float S = 0.f, acc[DD];
            #pragma unroll
            for (int d = 0; d < DD; d++) acc[d] = 0.f;
            #pragma unroll
            for (int q = 0; q < VSPLIT; q++) {      // fixed order -> deterministic
                S += __ldcg(&g_part[(q*17 + 0)*NTOK + tok]);
                #pragma unroll
                for (int d = 0; d < DD; d++)
                    acc[d] += __ldcg(&g_part[(q*17 + 1 + d)*NTOK + tok]);
            }
            float invS   = 1.f / S;
            float invden = 1.f / (1.f - t + 1e-10f);
            const float4* xi4 = (const float4*)(x_in + tok*DD);
            const float4* xb4 = (const float4*)(g_x  + tok*DD);
            float4 o[4]; float* of = (float*)o;
            #pragma unroll
            for (int i = 0; i < 4; i++) {
                float4 xi = xi4[i], xbs = xb4[i];
                float xiv[4] = {xi.x, xi.y, xi.z, xi.w};
                float xbv[4] = {xbs.x, xbs.y, xbs.z, xbs.w};
                #pragma unroll
                for (int jj = 0; jj < 4; jj++) {
                    int d = 4*i + jj;
                    of[d] = fmaf(coef, (acc[d]*invS - xiv[jj]) * invden, xbv[jj]);
                }
            }
            float4* xo4 = (float4*)(x_out + tok*DD);
            #pragma unroll
            for (int i = 0; i < 4; i++) xo4[i] = o[i];
        }
        if (tid == 0) g_ticket[tb] = 0;   // reset for next launch / replay
    }
}

// VQ argmin_v ||c_v||^2 - 2 x.c_v
__global__ __launch_bounds__(256)
void quantize_kernel(const float* __restrict__ CB,
                     float* __restrict__ out_x,
                     float* __restrict__ out_idx)
{
    __shared__ __align__(16) float smem[256*DD + 256];
    float* CBsm = smem;
    float* cn2  = smem + 256*DD;

    int tid   = threadIdx.x;
    int tokl  = tid & 63;
    int slice = tid >> 6;
    int tok   = blockIdx.x * 64 + tokl;

    float x[DD];
    {
        const float4* xi4 = (const float4*)(g_x + tok*DD);
        #pragma unroll
        for (int i = 0; i < 4; i++) {
            float4 v4 = xi4[i];
            x[4*i+0]=v4.x; x[4*i+1]=v4.y; x[4*i+2]=v4.z; x[4*i+3]=v4.w;
        }
    }

    float best = 3.4e38f;
    int   bidx = 0;

    for (int c0 = 0; c0 < VV; c0 += 256) {
        __syncthreads();
        {
            const float4* src = (const float4*)(CB + (size_t)c0*DD);
            float4* dst = (float4*)CBsm;
            for (int j = tid; j < 256*DD/4; j += 256) dst[j] = src[j];
        }
        {
            const float* row = CB + (size_t)(c0 + tid)*DD;
            float acc = 0.f;
            #pragma unroll
            for (int d = 0; d < DD; d++) acc = fmaf(row[d], row[d], acc);
            cn2[tid] = acc;
        }
        __syncthreads();

        int vbeg = slice * 64;
        for (int vi = 0; vi < 64; vi++) {
            int v = vbeg + vi;
            const float4* cb4 = (const float4*)(CBsm + v*DD);
            float4 cA=cb4[0], cB4=cb4[1], cC=cb4[2], cD4=cb4[3];
            float a0 = x[0]*cA.x  + x[1]*cA.y  + x[2]*cA.z  + x[3]*cA.w;
            float a1 = x[4]*cB4.x + x[5]*cB4.y + x[6]*cB4.z + x[7]*cB4.w;
            float a2 = x[8]*cC.x  + x[9]*cC.y  + x[10]*cC.z + x[11]*cC.w;
            float a3 = x[12]*cD4.x+ x[13]*cD4.y+ x[14]*cD4.z+ x[15]*cD4.w;
            float dist = cn2[v] - 2.f*((a0+a1) + (a2+a3));
            if (dist < best) { best = dist; bidx = c0 + v; }
        }
    }

    __syncthreads();
    float* redf = smem;
    redf[tid*2] = best;
    ((int*)redf)[tid*2 + 1] = bidx;
    __syncthreads();

    if (slice == 0) {
        float bb = best; int bi = bidx;
        #pragma unroll
        for (int q = 1; q < 4; q++) {
            float dq = redf[(tokl + 64*q)*2];
            int   iq = ((int*)redf)[(tokl + 64*q)*2 + 1];
            if (dq < bb || (dq == bb && iq < bi)) { bb = dq; bi = iq; }
        }
        if (out_idx) out_idx[tok] = (float)bi;
        if (out_x) {
            const float4* xi4 = (const float4*)(g_x + tok*DD);
            float4* o4 = (float4*)(out_x + tok*DD);
            #pragma unroll
            for (int i = 0; i < 4; i++) o4[i] = xi4[i];
        }
    }
}

extern "C" void kernel_launch(void* const* d_in, const int* in_sizes, int n_in,
                              void* d_out, int out_size) {
    const float* x0 = (const float*)d_in[0];
    const float* CB = (const float*)d_in[1];
    const float* W  = (const float*)d_in[2];
    const float* b  = (const float*)d_in[3];
    const float* tp = (const float*)d_in[4];

    copy_kernel<<<(NTOK*DD + 255)/256, 256>>>(x0, NTOK*DD);
    prep_frag<<<(NUNITS*32)/256, 256>>>(W, CB);

    const float dt = 1.0f / 7.0f;
    for (int k = 0; k < 7; k++) {
        float t = (float)k / 7.0f;
        velocity_kernel<<<NBLOCKS, NTHREADS>>>(b, tp, t,           0.5f*dt, 0);
        velocity_kernel<<<NBLOCKS, NTHREADS>>>(b, tp, t + 0.5f*dt, dt,      1);
    }

    float* out = (float*)d_out;
    if (out_size >= NTOK*DD + NTOK) {
        quantize_kernel<<<NTOK/64, 256>>>(CB, out, out + NTOK*DD);
    } else if (out_size == NTOK*DD) {
        quantize_kernel<<<NTOK/64, 256>>>(CB, out, nullptr);
    } else {
        quantize_kernel<<<NTOK/64, 256>>>(CB, nullptr, out);
    }
}

// round 13
// speedup vs baseline: 2.3014x; 1.0302x over previous
#include <cuda_runtime.h>

// Fixed shapes: B=32,S=256 -> NTOK=8192; D=16; V=8192; n_steps=8
#define NTOK 8192
#define DD   16
#define VV   8192
#define VC   128             // v per chunk = 8 units of 16 v, double-buffered
#define NTHREADS 256
#define WARPS 8
#define TPC  128             // 8 warps x 16 tokens
#define NTB  (NTOK/TPC)      // 64 token blocks
#define VSPLIT 4
#define VPER (VV/VSPLIT)     // 2048
#define NCHUNK (VPER/VC)     // 16
#define NBLOCKS (NTB*VSPLIT) // 256 CTAs (co-resident: 2/SM x 148 = 296)
#define UPCH 8               // 16-v units per chunk
#define NUNITS (VV/16)       // 512
#define NEVAL 14

#define INVT  1.25f
#define LOG2E 1.4426950408889634f
#define LSCALE (INVT*LOG2E)

typedef unsigned int u32;

// Scratch (allocation-free rule)
__device__ float g_x [NTOK*DD];
__device__ float g_xm[NTOK*DD];
// Per 16-v unit: 512 u32 (2KB) bf16 fragment pack:
// [0:128) W tile0  [128:256) W tile1  [256:384) CB d0..7  [384:512) CB d8..15
__device__ u32  g_frag[NUNITS*512];
__device__ float g_part[VSPLIT*17*NTOK];
__device__ int   g_ticket[NTB];   // monotonic arrivals (reset in-kernel)
__device__ int   g_done[NTB];     // last finalized eval+1 (reset in-kernel)
__device__ int   g_fin[NTB];      // exit counter for reset (reset in-kernel)

__device__ __forceinline__ float ex2f(float x) {
    float r; asm("ex2.approx.ftz.f32 %0, %1;" : "=f"(r) : "f"(x)); return r;
}
__device__ __forceinline__ u32 prmt_hi(float a, float b) {
    u32 r; asm("prmt.b32 %0, %1, %2, 0x7632;" : "=r"(r)
               : "r"(__float_as_uint(a)), "r"(__float_as_uint(b))); return r;
}
__device__ __forceinline__ u32 cvtb2(float hi, float lo) {
    u32 r; asm("cvt.rn.bf16x2.f32 %0, %1, %2;" : "=r"(r) : "f"(hi), "f"(lo)); return r;
}
__device__ __forceinline__ float trunc16(float a) {
    return __uint_as_float(__float_as_uint(a) & 0xffff0000u);
}
#define MMAB(d0,d1,d2,d3,a0,a1,a2,a3,b0,b1) \
    asm("mma.sync.aligned.m16n8k16.row.col.f32.bf16.bf16.f32 " \
        "{%0,%1,%2,%3},{%4,%5,%6,%7},{%8,%9},{%0,%1,%2,%3};" \
        : "+f"(d0),"+f"(d1),"+f"(d2),"+f"(d3) \
        : "r"(a0),"r"(a1),"r"(a2),"r"(a3),"r"(b0),"r"(b1))

#define CPA16(dst,src)  asm volatile("cp.async.cg.shared.global [%0],[%1],16;" :: "r"(dst), "l"(src))
#define CPA_COMMIT()    asm volatile("cp.async.commit_group;" ::: "memory")
#define CPA_WAIT0()     asm volatile("cp.async.wait_group 0;" ::: "memory")

// Pre-bake W' = W*LSCALE and CB into bf16 hi/lo m16n8k16 B-fragments.
__global__ void prep_frag(const float* __restrict__ W,   // [DD][VV]
                          const float* __restrict__ CB)  // [VV][DD]
{
    int gid  = blockIdx.x * blockDim.x + threadIdx.x;    // NUNITS*32
    int unit = gid >> 5;
    int lane = gid & 31;
    if (unit >= NUNITS) return;
    int g   = lane >> 2;
    int tig = lane & 3;
    int v0  = unit * 16;
    u32* out = g_frag + unit*512;

    #pragma unroll
    for (int T = 0; T < 2; T++) {
        int v = v0 + 8*T + g;
        float w0 = W[(2*tig    )*VV + v] * LSCALE;
        float w1 = W[(2*tig + 1)*VV + v] * LSCALE;
        float w2 = W[(2*tig + 8)*VV + v] * LSCALE;
        float w3 = W[(2*tig + 9)*VV + v] * LSCALE;
        out[T*128 + lane*4 + 0] = prmt_hi(w0, w1);
        out[T*128 + lane*4 + 1] = prmt_hi(w2, w3);
        out[T*128 + lane*4 + 2] = cvtb2(w1 - trunc16(w1), w0 - trunc16(w0));
        out[T*128 + lane*4 + 3] = cvtb2(w3 - trunc16(w3), w2 - trunc16(w2));
    }
    #pragma unroll
    for (int h = 0; h < 2; h++) {
        int d = 8*h + g;
        float c0 = CB[(v0 + 2*tig    )*DD + d];
        float c1 = CB[(v0 + 2*tig + 1)*DD + d];
        float c2 = CB[(v0 + 2*tig + 8)*DD + d];
        float c3 = CB[(v0 + 2*tig + 9)*DD + d];
        out[256 + h*128 + lane*4 + 0] = prmt_hi(c0, c1);
        out[256 + h*128 + lane*4 + 1] = prmt_hi(c2, c3);
        out[256 + h*128 + lane*4 + 2] = cvtb2(c1 - trunc16(c1), c0 - trunc16(c0));
        out[256 + h*128 + lane*4 + 3] = cvtb2(c3 - trunc16(c3), c2 - trunc16(c2));
    }
}

// Persistent midpoint integrator: all 14 velocity evals in one kernel.
// Per token-block cross-CTA handshake between evals (release via g_done).
__global__ __launch_bounds__(NTHREADS, 2)
void velocity_persist(const float* __restrict__ x0,
                      const float* __restrict__ b,
                      const float* __restrict__ tp)
{
    __shared__ __align__(16) u32 buf[2][UPCH*512];   // 2 x 16KB frag chunks
    __shared__ float csm[2][VC];
    __shared__ int flag;

    int tid  = threadIdx.x;
    int lane = tid & 31;
    int warp = tid >> 5;
    int g    = lane >> 2;
    int tig  = lane & 3;
    int tb   = blockIdx.x >> 2;
    int slot = blockIdx.x & 3;
    int tok0 = tb*TPC + warp*16;

    int vbase   = slot * VPER;
    int unitbeg = vbase >> 4;
    const float dtc = 1.0f / 7.0f;

    for (int e = 0; e < NEVAL; e++) {
        int   k    = e >> 1;
        int   half = e & 1;
        float t0   = (float)k / 7.0f;
        float t    = half ? (t0 + 0.5f*dtc) : t0;
        float coef = half ? dtc : 0.5f*dtc;
        const float* x_in   = half ? g_xm : (k == 0 ? x0 : g_x);
        const float* x_base = (k == 0) ? x0 : g_x;
        float*       x_out  = half ? g_x  : g_xm;

        // X A-fragments (bf16 hi/lo)
        u32 xhi[4], xlo[4];
        {
            const float* x0p = x_in + (tok0 + g    )*DD;
            const float* x8p = x_in + (tok0 + g + 8)*DD;
            float v0 = x0p[2*tig],     v1 = x0p[2*tig + 1];
            float v2 = x8p[2*tig],     v3 = x8p[2*tig + 1];
            float v4 = x0p[2*tig + 8], v5 = x0p[2*tig + 9];
            float v6 = x8p[2*tig + 8], v7 = x8p[2*tig + 9];
            xhi[0] = prmt_hi(v0, v1);  xhi[1] = prmt_hi(v2, v3);
            xhi[2] = prmt_hi(v4, v5);  xhi[3] = prmt_hi(v6, v7);
            xlo[0] = cvtb2(v1 - trunc16(v1), v0 - trunc16(v0));
            xlo[1] = cvtb2(v3 - trunc16(v3), v2 - trunc16(v2));
            xlo[2] = cvtb2(v5 - trunc16(v5), v4 - trunc16(v4));
            xlo[3] = cvtb2(v7 - trunc16(v7), v6 - trunc16(v6));
        }

        float muE[8], muO[8];
        #pragma unroll
        for (int i = 0; i < 8; i++) { muE[i] = 0.f; muO[i] = 0.f; }
        float sA = 0.f, sB = 0.f;

        // Prologue: prefetch chunk 0 (16KB = 64B/thread) + bias regs
        {
            u32 d0 = (u32)__cvta_generic_to_shared(&buf[0][0]) + tid*16;
            const char* s0 = (const char*)(g_frag + (size_t)unitbeg*512) + tid*16;
            #pragma unroll
            for (int kk = 0; kk < 4; kk++) CPA16(d0 + kk*NTHREADS*16, s0 + kk*NTHREADS*16);
            CPA_COMMIT();
        }
        float rb = 0.f, rtp = 0.f;
        if (tid < VC) { rb = b[vbase+tid]; rtp = tp[vbase+tid]; }

        for (int ci = 0; ci < NCHUNK; ci++) {
            int cur = ci & 1;
            CPA_WAIT0();
            if (tid < VC) csm[cur][tid] = (rb + t*rtp) * LSCALE;
            __syncthreads();

            if (ci + 1 < NCHUNK) {
                int unext = unitbeg + (ci+1)*UPCH;
                u32 d1 = (u32)__cvta_generic_to_shared(&buf[cur^1][0]) + tid*16;
                const char* s1 = (const char*)(g_frag + (size_t)unext*512) + tid*16;
                #pragma unroll
                for (int kk = 0; kk < 4; kk++) CPA16(d1 + kk*NTHREADS*16, s1 + kk*NTHREADS*16);
                CPA_COMMIT();
                int c1 = vbase + (ci+1)*VC;
                if (tid < VC) { rb = b[c1+tid]; rtp = tp[c1+tid]; }
            }

            const u32*   bufc = buf[cur];
            const float* csmc = csm[cur];
            #pragma unroll
            for (int uu = 0; uu < UPCH; uu++) {
                const u32* ub = bufc + uu*512;
                uint4 wt0 = *(const uint4*)(ub +        lane*4);
                uint4 wt1 = *(const uint4*)(ub + 128 +  lane*4);
                uint4 cb0 = *(const uint4*)(ub + 256 +  lane*4);
                uint4 cb1 = *(const uint4*)(ub + 384 +  lane*4);
                float* mu = (uu & 1) ? muO : muE;

                float s0=0.f, s1=0.f, s2=0.f, s3=0.f;
                float r0=0.f, r1=0.f, r2=0.f, r3=0.f;
                MMAB(s0,s1,s2,s3, xhi[0],xhi[1],xhi[2],xhi[3], wt0.x, wt0.y);
                MMAB(r0,r1,r2,r3, xhi[0],xhi[1],xhi[2],xhi[3], wt1.x, wt1.y);
                MMAB(s0,s1,s2,s3, xlo[0],xlo[1],xlo[2],xlo[3], wt0.x, wt0.y);
                MMAB(r0,r1,r2,r3, xlo[0],xlo[1],xlo[2],xlo[3], wt1.x, wt1.y);
                MMAB(s0,s1,s2,s3, xhi[0],xhi[1],xhi[2],xhi[3], wt0.z, wt0.w);
                MMAB(r0,r1,r2,r3, xhi[0],xhi[1],xhi[2],xhi[3], wt1.z, wt1.w);

                int voff = uu*16;
                float2 bb0 = *(const float2*)(csmc + voff +     2*tig);
                float2 bb1 = *(const float2*)(csmc + voff + 8 + 2*tig);
                float p0 = ex2f(s0 + bb0.x), p1 = ex2f(s1 + bb0.y);
                float p2 = ex2f(s2 + bb0.x), p3 = ex2f(s3 + bb0.y);
                float q0 = ex2f(r0 + bb1.x), q1 = ex2f(r1 + bb1.y);
                float q2 = ex2f(r2 + bb1.x), q3 = ex2f(r3 + bb1.y);
                sA += (p0 + p1) + (q0 + q1);
                sB += (p2 + p3) + (q2 + q3);

                u32 ph0 = prmt_hi(p0, p1), ph1 = prmt_hi(p2, p3);
                u32 ph2 = prmt_hi(q0, q1), ph3 = prmt_hi(q2, q3);
                u32 pl0 = cvtb2(p1 - trunc16(p1), p0 - trunc16(p0));
                u32 pl1 = cvtb2(p3 - trunc16(p3), p2 - trunc16(p2));
                u32 pl2 = cvtb2(q1 - trunc16(q1), q0 - trunc16(q0));
                u32 pl3 = cvtb2(q3 - trunc16(q3), q2 - trunc16(q2));

                MMAB(mu[0],mu[1],mu[2],mu[3], ph0,ph1,ph2,ph3, cb0.x, cb0.y);
                MMAB(mu[4],mu[5],mu[6],mu[7], ph0,ph1,ph2,ph3, cb1.x, cb1.y);
                MMAB(mu[0],mu[1],mu[2],mu[3], pl0,pl1,pl2,pl3, cb0.x, cb0.y);
                MMAB(mu[4],mu[5],mu[6],mu[7], pl0,pl1,pl2,pl3, cb1.x, cb1.y);
                MMAB(mu[0],mu[1],mu[2],mu[3], ph0,ph1,ph2,ph3, cb0.z, cb0.w);
                MMAB(mu[4],mu[5],mu[6],mu[7], ph0,ph1,ph2,ph3, cb1.z, cb1.w);
            }
            __syncthreads();
        }

        float mu[8];
        #pragma unroll
        for (int i = 0; i < 8; i++) mu[i] = muE[i] + muO[i];

        sA += __shfl_xor_sync(0xffffffffu, sA, 1);
        sA += __shfl_xor_sync(0xffffffffu, sA, 2);
        sB += __shfl_xor_sync(0xffffffffu, sB, 1);
        sB += __shfl_xor_sync(0xffffffffu, sB, 2);

        int tokg  = tok0 + g;
        int tokg8 = tokg + 8;
        if (tig == 0) {
            g_part[(slot*17 + 0)*NTOK + tokg ] = sA;
            g_part[(slot*17 + 0)*NTOK + tokg8] = sB;
        }
        {
            int d0 = 2*tig, d1 = 2*tig + 1;
            g_part[(slot*17 + 1 + d0    )*NTOK + tokg ] = mu[0];
            g_part[(slot*17 + 1 + d1    )*NTOK + tokg ] = mu[1];
            g_part[(slot*17 + 1 + d0    )*NTOK + tokg8] = mu[2];
            g_part[(slot*17 + 1 + d1    )*NTOK + tokg8] = mu[3];
            g_part[(slot*17 + 1 + 8 + d0)*NTOK + tokg ] = mu[4];
            g_part[(slot*17 + 1 + 8 + d1)*NTOK + tokg ] = mu[5];
            g_part[(slot*17 + 1 + 8 + d0)*NTOK + tokg8] = mu[6];
            g_part[(slot*17 + 1 + 8 + d1)*NTOK + tokg8] = mu[7];
        }

        // Per-token-block handshake: last-arriving CTA finalizes x_out,
        // then releases g_done[tb] = e+1 for the other three.
        __threadfence();
        __syncthreads();
        if (tid == 0) flag = (atomicAdd(&g_ticket[tb], 1) == 4*e + 3);
        __syncthreads();
        if (flag) {
            __threadfence();
            if (tid < TPC) {
                int tok = tb*TPC + tid;
                float S = 0.f, acc[DD];
                #pragma unroll
                for (int d = 0; d < DD; d++) acc[d] = 0.f;
                #pragma unroll
                for (int q = 0; q < VSPLIT; q++) {   // fixed order -> deterministic
                    S += __ldcg(&g_part[(q*17 + 0)*NTOK + tok]);
                    #pragma unroll
                    for (int d = 0; d < DD; d++)
                        acc[d] += __ldcg(&g_part[(q*17 + 1 + d)*NTOK + tok]);
                }
                float invS   = 1.f / S;
                float invden = 1.f / (1.f - t + 1e-10f);
                const float4* xi4 = (const float4*)(x_in   + tok*DD);
                const float4* xb4 = (const float4*)(x_base + tok*DD);
                float4 o[4]; float* of = (float*)o;
                #pragma unroll
                for (int i = 0; i < 4; i++) {
                    float4 xi = xi4[i], xbs = xb4[i];
                    float xiv[4] = {xi.x, xi.y, xi.z, xi.w};
                    float xbv[4] = {xbs.x, xbs.y, xbs.z, xbs.w};
                    #pragma unroll
                    for (int jj = 0; jj < 4; jj++) {
                        int d = 4*i + jj;
                        of[d] = fmaf(coef, (acc[d]*invS - xiv[jj]) * invden, xbv[jj]);
                    }
                }
                float4* xo4 = (float4*)(x_out + tok*DD);
                #pragma unroll
                for (int i = 0; i < 4; i++) xo4[i] = o[i];
            }
            __syncthreads();
            if (tid == 0) {
                __threadfence();                    // release x_out
                atomicExch(&g_done[tb], e + 1);
            }
        }
        // Acquire: wait until this eval's x_out is published
        if (tid == 0) {
            while (atomicAdd(&g_done[tb], 0) < e + 1) __nanosleep(64);
        }
        __syncthreads();
        __threadfence();
    }

    // Reset counters for next launch / graph replay (after all 4 CTAs exit spin)
    if (tid == 0) {
        if (atomicAdd(&g_fin[tb], 1) == 3) {
            g_ticket[tb] = 0;
            g_done[tb]   = 0;
            g_fin[tb]    = 0;
            __threadfence();
        }
    }
}

// VQ argmin_v ||c_v||^2 - 2 x.c_v
__global__ __launch_bounds__(256)
void quantize_kernel(const float* __restrict__ CB,
                     float* __restrict__ out_x,
                     float* __restrict__ out_idx)
{
    __shared__ __align__(16) float smem[256*DD + 256];
    float* CBsm = smem;
    float* cn2  = smem + 256*DD;

    int tid   = threadIdx.x;
    int tokl  = tid & 63;
    int slice = tid >> 6;
    int tok   = blockIdx.x * 64 + tokl;

    float x[DD];
    {
        const float4* xi4 = (const float4*)(g_x + tok*DD);
        #pragma unroll
        for (int i = 0; i < 4; i++) {
            float4 v4 = xi4[i];
            x[4*i+0]=v4.x; x[4*i+1]=v4.y; x[4*i+2]=v4.z; x[4*i+3]=v4.w;
        }
    }

    float best = 3.4e38f;
    int   bidx = 0;

    for (int c0 = 0; c0 < VV; c0 += 256) {
        __syncthreads();
        {
            const float4* src = (const float4*)(CB + (size_t)c0*DD);
            float4* dst = (float4*)CBsm;
            for (int j = tid; j < 256*DD/4; j += 256) dst[j] = src[j];
        }
        {
            const float* row = CB + (size_t)(c0 + tid)*DD;
            float acc = 0.f;
            #pragma unroll
            for (int d = 0; d < DD; d++) acc = fmaf(row[d], row[d], acc);
            cn2[tid] = acc;
        }
        __syncthreads();

        int vbeg = slice * 64;
        for (int vi = 0; vi < 64; vi++) {
            int v = vbeg + vi;
            const float4* cb4 = (const float4*)(CBsm + v*DD);
            float4 cA=cb4[0], cB4=cb4[1], cC=cb4[2], cD4=cb4[3];
            float a0 = x[0]*cA.x  + x[1]*cA.y  + x[2]*cA.z  + x[3]*cA.w;
            float a1 = x[4]*cB4.x + x[5]*cB4.y + x[6]*cB4.z + x[7]*cB4.w;
            float a2 = x[8]*cC.x  + x[9]*cC.y  + x[10]*cC.z + x[11]*cC.w;
            float a3 = x[12]*cD4.x+ x[13]*cD4.y+ x[14]*cD4.z+ x[15]*cD4.w;
            float dist = cn2[v] - 2.f*((a0+a1) + (a2+a3));
            if (dist < best) { best = dist; bidx = c0 + v; }
        }
    }

    __syncthreads();
    float* redf = smem;
    redf[tid*2] = best;
    ((int*)redf)[tid*2 + 1] = bidx;
    __syncthreads();

    if (slice == 0) {
        float bb = best; int bi = bidx;
        #pragma unroll
        for (int q = 1; q < 4; q++) {
            float dq = redf[(tokl + 64*q)*2];
            int   iq = ((int*)redf)[(tokl + 64*q)*2 + 1];
            if (dq < bb || (dq == bb && iq < bi)) { bb = dq; bi = iq; }
        }
        if (out_idx) out_idx[tok] = (float)bi;
        if (out_x) {
            const float4* xi4 = (const float4*)(g_x + tok*DD);
            float4* o4 = (float4*)(out_x + tok*DD);
            #pragma unroll
            for (int i = 0; i < 4; i++) o4[i] = xi4[i];
        }
    }
}

extern "C" void kernel_launch(void* const* d_in, const int* in_sizes, int n_in,
                              void* d_out, int out_size) {
    const float* x0 = (const float*)d_in[0];
    const float* CB = (const float*)d_in[1];
    const float* W  = (const float*)d_in[2];
    const float* b  = (const float*)d_in[3];
    const float* tp = (const float*)d_in[4];

    prep_frag<<<(NUNITS*32)/256, 256>>>(W, CB);
    velocity_persist<<<NBLOCKS, NTHREADS>>>(x0, b, tp);

    float* out = (float*)d_out;
    if (out_size >= NTOK*DD + NTOK) {
        quantize_kernel<<<NTOK/64, 256>>>(CB, out, out + NTOK*DD);
    } else if (out_size == NTOK*DD) {
        quantize_kernel<<<NTOK/64, 256>>>(CB, out, nullptr);
    } else {
        quantize_kernel<<<NTOK/64, 256>>>(CB, nullptr, out);
    }
}

// round 17
// speedup vs baseline: 2.7639x; 1.2010x over previous
#include <cuda_runtime.h>

// Fixed shapes: B=32,S=256 -> NTOK=8192; D=16; V=8192; n_steps=8
#define NTOK 8192
#define DD   16
#define VV   8192
#define VC   128             // v per chunk = 8 units of 16 v, double-buffered
#define NTHREADS 256
#define WARPS 8
#define TPC  128             // 8 warps x 16 tokens
#define NTB  (NTOK/TPC)      // 64 token blocks
#define VSPLIT 4
#define VPER (VV/VSPLIT)     // 2048
#define NCHUNK (VPER/VC)     // 16
#define NBLOCKS (NTB*VSPLIT) // 256 CTAs (co-resident: 2/SM x 148 = 296)
#define UPCH 8               // 16-v units per chunk
#define NUNITS (VV/16)       // 512
#define UNITW 512            // u32 per unit (2KB): W hi/lo 256 + CB hi/lo 256
#define QUNITW 256           // u32 per unit for quantize CBq (k=dims) hi/lo
#define NEVAL 14

#define INVT  1.25f
#define LOG2E 1.4426950408889634f
#define LSCALE (INVT*LOG2E)

typedef unsigned int u32;

// Scratch (allocation-free rule)
__device__ float g_x [NTOK*DD];
__device__ float g_xm[NTOK*DD];
// Velocity fragments (R12 layout, exact): per unit 512 u32:
// [0:128) W t0 hi/lo  [128:256) W t1 hi/lo  [256:384) CB hi  [384:512) CB lo
__device__ u32  g_frag [NUNITS*UNITW];
// Quantize fragments: CBq with k=dims (W-style), hi/lo: per unit 256 u32
__device__ u32  g_qfrag[NUNITS*QUNITW];
__device__ float g_cn2 [VV];            // exact ||c_v||^2
__device__ float g_part[VSPLIT*17*NTOK];
__device__ int   g_ticket[NTB];
__device__ int   g_done[NTB];
__device__ int   g_fin[NTB];

__device__ __forceinline__ float ex2f(float x) {
    float r; asm("ex2.approx.ftz.f32 %0, %1;" : "=f"(r) : "f"(x)); return r;
}
__device__ __forceinline__ u32 prmt_hi(float a, float b) {   // truncated pack
    u32 r; asm("prmt.b32 %0, %1, %2, 0x7632;" : "=r"(r)
               : "r"(__float_as_uint(a)), "r"(__float_as_uint(b))); return r;
}
__device__ __forceinline__ u32 cvtb2(float hi, float lo) {   // rounded pack
    u32 r; asm("cvt.rn.bf16x2.f32 %0, %1, %2;" : "=r"(r) : "f"(hi), "f"(lo)); return r;
}
__device__ __forceinline__ float trunc16(float a) {
    return __uint_as_float(__float_as_uint(a) & 0xffff0000u);
}
#define MMAB(d0,d1,d2,d3,a0,a1,a2,a3,b0,b1) \
    asm("mma.sync.aligned.m16n8k16.row.col.f32.bf16.bf16.f32 " \
        "{%0,%1,%2,%3},{%4,%5,%6,%7},{%8,%9},{%0,%1,%2,%3};" \
        : "+f"(d0),"+f"(d1),"+f"(d2),"+f"(d3) \
        : "r"(a0),"r"(a1),"r"(a2),"r"(a3),"r"(b0),"r"(b1))

#define CPA16(dst,src)  asm volatile("cp.async.cg.shared.global [%0],[%1],16;" :: "r"(dst), "l"(src))
#define CPA_COMMIT()    asm volatile("cp.async.commit_group;" ::: "memory")
#define CPA_WAIT0()     asm volatile("cp.async.wait_group 0;" ::: "memory")

// Pre-bake: W' (hi/lo), CB k=v frags (hi/lo), CBq k=dims frags (hi/lo), cn2.
__global__ void prep_frag(const float* __restrict__ W,   // [DD][VV]
                          const float* __restrict__ CB)  // [VV][DD]
{
    int gid  = blockIdx.x * blockDim.x + threadIdx.x;    // NUNITS*32
    int unit = gid >> 5;
    int lane = gid & 31;
    if (unit >= NUNITS) return;
    int g   = lane >> 2;
    int tig = lane & 3;
    int v0  = unit * 16;
    u32* out  = g_frag  + unit*UNITW;
    u32* outq = g_qfrag + unit*QUNITW;

    // W tiles (k=dims), hi truncated / lo remainder
    #pragma unroll
    for (int T = 0; T < 2; T++) {
        int v = v0 + 8*T + g;
        float w0 = W[(2*tig    )*VV + v] * LSCALE;
        float w1 = W[(2*tig + 1)*VV + v] * LSCALE;
        float w2 = W[(2*tig + 8)*VV + v] * LSCALE;
        float w3 = W[(2*tig + 9)*VV + v] * LSCALE;
        out[T*128 + lane*4 + 0] = prmt_hi(w0, w1);
        out[T*128 + lane*4 + 1] = prmt_hi(w2, w3);
        out[T*128 + lane*4 + 2] = cvtb2(w1 - trunc16(w1), w0 - trunc16(w0));
        out[T*128 + lane*4 + 3] = cvtb2(w3 - trunc16(w3), w2 - trunc16(w2));
    }
    // CB k=v frags (hi truncated / lo remainder), cols d = g / 8+g
    {
        float c0 = CB[(v0 + 2*tig    )*DD + g];
        float c1 = CB[(v0 + 2*tig + 1)*DD + g];
        float c2 = CB[(v0 + 2*tig + 8)*DD + g];
        float c3 = CB[(v0 + 2*tig + 9)*DD + g];
        float d0 = CB[(v0 + 2*tig    )*DD + 8 + g];
        float d1 = CB[(v0 + 2*tig + 1)*DD + 8 + g];
        float d2 = CB[(v0 + 2*tig + 8)*DD + 8 + g];
        float d3 = CB[(v0 + 2*tig + 9)*DD + 8 + g];
        out[256 + lane*4 + 0] = prmt_hi(c0, c1);
        out[256 + lane*4 + 1] = prmt_hi(c2, c3);
        out[256 + lane*4 + 2] = prmt_hi(d0, d1);
        out[256 + lane*4 + 3] = prmt_hi(d2, d3);
        out[384 + lane*4 + 0] = cvtb2(c1 - trunc16(c1), c0 - trunc16(c0));
        out[384 + lane*4 + 1] = cvtb2(c3 - trunc16(c3), c2 - trunc16(c2));
        out[384 + lane*4 + 2] = cvtb2(d1 - trunc16(d1), d0 - trunc16(d0));
        out[384 + lane*4 + 3] = cvtb2(d3 - trunc16(d3), d2 - trunc16(d2));
    }
    // CBq tiles (k=dims, W-style) for the quantize GEMM
    #pragma unroll
    for (int T = 0; T < 2; T++) {
        int v = v0 + 8*T + g;
        float q0 = CB[v*DD + 2*tig    ];
        float q1 = CB[v*DD + 2*tig + 1];
        float q2 = CB[v*DD + 2*tig + 8];
        float q3 = CB[v*DD + 2*tig + 9];
        outq[T*128 + lane*4 + 0] = prmt_hi(q0, q1);
        outq[T*128 + lane*4 + 1] = prmt_hi(q2, q3);
        outq[T*128 + lane*4 + 2] = cvtb2(q1 - trunc16(q1), q0 - trunc16(q0));
        outq[T*128 + lane*4 + 3] = cvtb2(q3 - trunc16(q3), q2 - trunc16(q2));
    }
    // exact cn2
    if (lane < 16) {
        const float* row = CB + (size_t)(v0 + lane)*DD;
        float acc = 0.f;
        #pragma unroll
        for (int d = 0; d < DD; d++) acc = fmaf(row[d], row[d], acc);
        g_cn2[v0 + lane] = acc;
    }
}

// Persistent kernel: 14 velocity evals + fused tensor-core VQ quantize.
__global__ __launch_bounds__(NTHREADS, 2)
void velocity_persist(const float* __restrict__ x0,
                      const float* __restrict__ b,
                      const float* __restrict__ tp,
                      float* __restrict__ out_x,
                      float* __restrict__ out_idx)
{
    __shared__ __align__(16) u32 buf[2][UPCH*UNITW];   // 2 x 16KB
    __shared__ float csm[2][VC];
    __shared__ int flag;

    int tid  = threadIdx.x;
    int lane = tid & 31;
    int warp = tid >> 5;
    int g    = lane >> 2;
    int tig  = lane & 3;
    int tb   = blockIdx.x >> 2;
    int slot = blockIdx.x & 3;
    int tok0 = tb*TPC + warp*16;

    int vbase   = slot * VPER;
    int unitbeg = vbase >> 4;
    const float dtc = 1.0f / 7.0f;

    for (int e = 0; e < NEVAL; e++) {
        int   k    = e >> 1;
        int   half = e & 1;
        float t0   = (float)k / 7.0f;
        float t    = half ? (t0 + 0.5f*dtc) : t0;
        float coef = half ? dtc : 0.5f*dtc;
        const float* x_in   = half ? g_xm : (k == 0 ? x0 : g_x);
        const float* x_base = (k == 0) ? x0 : g_x;
        float*       x_out  = half ? g_x  : g_xm;

        u32 xhi[4], xlo[4];
        {
            const float* x0p = x_in + (tok0 + g    )*DD;
            const float* x8p = x_in + (tok0 + g + 8)*DD;
            float v0 = x0p[2*tig],     v1 = x0p[2*tig + 1];
            float v2 = x8p[2*tig],     v3 = x8p[2*tig + 1];
            float v4 = x0p[2*tig + 8], v5 = x0p[2*tig + 9];
            float v6 = x8p[2*tig + 8], v7 = x8p[2*tig + 9];
            xhi[0] = prmt_hi(v0, v1);  xhi[1] = prmt_hi(v2, v3);
            xhi[2] = prmt_hi(v4, v5);  xhi[3] = prmt_hi(v6, v7);
            xlo[0] = cvtb2(v1 - trunc16(v1), v0 - trunc16(v0));
            xlo[1] = cvtb2(v3 - trunc16(v3), v2 - trunc16(v2));
            xlo[2] = cvtb2(v5 - trunc16(v5), v4 - trunc16(v4));
            xlo[3] = cvtb2(v7 - trunc16(v7), v6 - trunc16(v6));
        }

        float muE[8], muO[8];
        #pragma unroll
        for (int i = 0; i < 8; i++) { muE[i] = 0.f; muO[i] = 0.f; }
        float sA = 0.f, sB = 0.f;

        {
            u32 d0 = (u32)__cvta_generic_to_shared(&buf[0][0]) + tid*16;
            const char* s0 = (const char*)(g_frag + (size_t)unitbeg*UNITW) + tid*16;
            #pragma unroll
            for (int kk = 0; kk < 4; kk++) CPA16(d0 + kk*NTHREADS*16, s0 + kk*NTHREADS*16);
            CPA_COMMIT();
        }
        float rb = 0.f, rtp = 0.f;
        if (tid < VC) { rb = b[vbase+tid]; rtp = tp[vbase+tid]; }

        for (int ci = 0; ci < NCHUNK; ci++) {
            int cur = ci & 1;
            CPA_WAIT0();
            if (tid < VC) csm[cur][tid] = (rb + t*rtp) * LSCALE;
            __syncthreads();

            if (ci + 1 < NCHUNK) {
                int unext = unitbeg + (ci+1)*UPCH;
                u32 d1 = (u32)__cvta_generic_to_shared(&buf[cur^1][0]) + tid*16;
                const char* s1 = (const char*)(g_frag + (size_t)unext*UNITW) + tid*16;
                #pragma unroll
                for (int kk = 0; kk < 4; kk++) CPA16(d1 + kk*NTHREADS*16, s1 + kk*NTHREADS*16);
                CPA_COMMIT();
                int c1 = vbase + (ci+1)*VC;
                if (tid < VC) { rb = b[c1+tid]; rtp = tp[c1+tid]; }
            }

            const u32*   bufc = buf[cur];
            const float* csmc = csm[cur];
            #pragma unroll
            for (int uu = 0; uu < UPCH; uu++) {
                const u32* ub = bufc + uu*UNITW;
                uint4 wt0 = *(const uint4*)(ub +        lane*4);
                uint4 wt1 = *(const uint4*)(ub + 128 +  lane*4);
                uint4 cbh = *(const uint4*)(ub + 256 +  lane*4);  // CB hi
                uint4 cbl = *(const uint4*)(ub + 384 +  lane*4);  // CB lo
                float* mu = (uu & 1) ? muO : muE;

                float s0=0.f, s1=0.f, s2=0.f, s3=0.f;
                float r0=0.f, r1=0.f, r2=0.f, r3=0.f;
                MMAB(s0,s1,s2,s3, xhi[0],xhi[1],xhi[2],xhi[3], wt0.x, wt0.y);
                MMAB(r0,r1,r2,r3, xhi[0],xhi[1],xhi[2],xhi[3], wt1.x, wt1.y);
                MMAB(s0,s1,s2,s3, xlo[0],xlo[1],xlo[2],xlo[3], wt0.x, wt0.y);
                MMAB(r0,r1,r2,r3, xlo[0],xlo[1],xlo[2],xlo[3], wt1.x, wt1.y);
                MMAB(s0,s1,s2,s3, xhi[0],xhi[1],xhi[2],xhi[3], wt0.z, wt0.w);
                MMAB(r0,r1,r2,r3, xhi[0],xhi[1],xhi[2],xhi[3], wt1.z, wt1.w);

                int voff = uu*16;
                float2 bb0 = *(const float2*)(csmc + voff +     2*tig);
                float2 bb1 = *(const float2*)(csmc + voff + 8 + 2*tig);
                float p0 = ex2f(s0 + bb0.x), p1 = ex2f(s1 + bb0.y);
                float p2 = ex2f(s2 + bb0.x), p3 = ex2f(s3 + bb0.y);
                float q0 = ex2f(r0 + bb1.x), q1 = ex2f(r1 + bb1.y);
                float q2 = ex2f(r2 + bb1.x), q3 = ex2f(r3 + bb1.y);
                sA += (p0 + p1) + (q0 + q1);
                sB += (p2 + p3) + (q2 + q3);

                // exact P hi/lo (truncated hi + rounded remainder)
                u32 ph0 = prmt_hi(p0, p1), ph1 = prmt_hi(p2, p3);
                u32 ph2 = prmt_hi(q0, q1), ph3 = prmt_hi(q2, q3);
                u32 pl0 = cvtb2(p1 - trunc16(p1), p0 - trunc16(p0));
                u32 pl1 = cvtb2(p3 - trunc16(p3), p2 - trunc16(p2));
                u32 pl2 = cvtb2(q1 - trunc16(q1), q0 - trunc16(q0));
                u32 pl3 = cvtb2(q3 - trunc16(q3), q2 - trunc16(q2));

                MMAB(mu[0],mu[1],mu[2],mu[3], ph0,ph1,ph2,ph3, cbh.x, cbh.y);
                MMAB(mu[4],mu[5],mu[6],mu[7], ph0,ph1,ph2,ph3, cbh.z, cbh.w);
                MMAB(mu[0],mu[1],mu[2],mu[3], pl0,pl1,pl2,pl3, cbh.x, cbh.y);
                MMAB(mu[4],mu[5],mu[6],mu[7], pl0,pl1,pl2,pl3, cbh.z, cbh.w);
                MMAB(mu[0],mu[1],mu[2],mu[3], ph0,ph1,ph2,ph3, cbl.x, cbl.y);
                MMAB(mu[4],mu[5],mu[6],mu[7], ph0,ph1,ph2,ph3, cbl.z, cbl.w);
            }
            __syncthreads();
        }

        float mu[8];
        #pragma unroll
        for (int i = 0; i < 8; i++) mu[i] = muE[i] + muO[i];

        sA += __shfl_xor_sync(0xffffffffu, sA, 1);
        sA += __shfl_xor_sync(0xffffffffu, sA, 2);
        sB += __shfl_xor_sync(0xffffffffu, sB, 1);
        sB += __shfl_xor_sync(0xffffffffu, sB, 2);

        int tokg  = tok0 + g;
        int tokg8 = tokg + 8;
        if (tig == 0) {
            g_part[(slot*17 + 0)*NTOK + tokg ] = sA;
            g_part[(slot*17 + 0)*NTOK + tokg8] = sB;
        }
        {
            int d0 = 2*tig, d1 = 2*tig + 1;
            g_part[(slot*17 + 1 + d0    )*NTOK + tokg ] = mu[0];
            g_part[(slot*17 + 1 + d1    )*NTOK + tokg ] = mu[1];
            g_part[(slot*17 + 1 + d0    )*NTOK + tokg8] = mu[2];
            g_part[(slot*17 + 1 + d1    )*NTOK + tokg8] = mu[3];
            g_part[(slot*17 + 1 + 8 + d0)*NTOK + tokg ] = mu[4];
            g_part[(slot*17 + 1 + 8 + d1)*NTOK + tokg ] = mu[5];
            g_part[(slot*17 + 1 + 8 + d0)*NTOK + tokg8] = mu[6];
            g_part[(slot*17 + 1 + 8 + d1)*NTOK + tokg8] = mu[7];
        }

        __threadfence();
        __syncthreads();
        if (tid == 0) flag = (atomicAdd(&g_ticket[tb], 1) == 4*e + 3);
        __syncthreads();
        if (flag) {
            __threadfence();
            if (tid < TPC) {
                int tok = tb*TPC + tid;
                float S = 0.f, acc[DD];
                #pragma unroll
                for (int d = 0; d < DD; d++) acc[d] = 0.f;
                #pragma unroll
                for (int q = 0; q < VSPLIT; q++) {
                    S += __ldcg(&g_part[(q*17 + 0)*NTOK + tok]);
                    #pragma unroll
                    for (int d = 0; d < DD; d++)
                        acc[d] += __ldcg(&g_part[(q*17 + 1 + d)*NTOK + tok]);
                }
                float invS   = 1.f / S;
                float invden = 1.f / (1.f - t + 1e-10f);
                const float4* xi4 = (const float4*)(x_in   + tok*DD);
                const float4* xb4 = (const float4*)(x_base + tok*DD);
                float4 o[4]; float* of = (float*)o;
                #pragma unroll
                for (int i = 0; i < 4; i++) {
                    float4 xi = xi4[i], xbs = xb4[i];
                    float xiv[4] = {xi.x, xi.y, xi.z, xi.w};
                    float xbv[4] = {xbs.x, xbs.y, xbs.z, xbs.w};
                    #pragma unroll
                    for (int jj = 0; jj < 4; jj++) {
                        int d = 4*i + jj;
                        of[d] = fmaf(coef, (acc[d]*invS - xiv[jj]) * invden, xbv[jj]);
                    }
                }
                float4* xo4 = (float4*)(x_out + tok*DD);
                #pragma unroll
                for (int i = 0; i < 4; i++) xo4[i] = o[i];
            }
            __syncthreads();
            if (tid == 0) {
                __threadfence();
                atomicExch(&g_done[tb], e + 1);
            }
        }
        if (tid == 0) {
            while (atomicAdd(&g_done[tb], 0) < e + 1) __nanosleep(64);
        }
        __syncthreads();
        __threadfence();
    }

    // ---- fused VQ quantize phase (tensor-core) ----
    {
        u32 xhi[4], xlo[4];
        {
            const float* x0p = g_x + (tok0 + g    )*DD;
            const float* x8p = g_x + (tok0 + g + 8)*DD;
            float v0 = x0p[2*tig],     v1 = x0p[2*tig + 1];
            float v2 = x8p[2*tig],     v3 = x8p[2*tig + 1];
            float v4 = x0p[2*tig + 8], v5 = x0p[2*tig + 9];
            float v6 = x8p[2*tig + 8], v7 = x8p[2*tig + 9];
            xhi[0] = prmt_hi(v0, v1);  xhi[1] = prmt_hi(v2, v3);
            xhi[2] = prmt_hi(v4, v5);  xhi[3] = prmt_hi(v6, v7);
            xlo[0] = cvtb2(v1 - trunc16(v1), v0 - trunc16(v0));
            xlo[1] = cvtb2(v3 - trunc16(v3), v2 - trunc16(v2));
            xlo[2] = cvtb2(v5 - trunc16(v5), v4 - trunc16(v4));
            xlo[3] = cvtb2(v7 - trunc16(v7), v6 - trunc16(v6));
        }
        float bestA = 3.4e38f, bestB = 3.4e38f;
        int   idxA = 0, idxB = 0;

        {   // prefetch chunk 0 of CBq (8KB = 32B/thread)
            u32 d0 = (u32)__cvta_generic_to_shared(&buf[0][0]) + tid*16;
            const char* s0 = (const char*)(g_qfrag + (size_t)unitbeg*QUNITW) + tid*16;
            #pragma unroll
            for (int kk = 0; kk < 2; kk++) CPA16(d0 + kk*NTHREADS*16, s0 + kk*NTHREADS*16);
            CPA_COMMIT();
        }
        float rc = 0.f;
        if (tid < VC) rc = g_cn2[vbase + tid];

        for (int ci = 0; ci < NCHUNK; ci++) {
            int cur = ci & 1;
            CPA_WAIT0();
            if (tid < VC) csm[cur][tid] = rc;
            __syncthreads();

            if (ci + 1 < NCHUNK) {
                int unext = unitbeg + (ci+1)*UPCH;
                u32 d1 = (u32)__cvta_generic_to_shared(&buf[cur^1][0]) + tid*16;
                const char* s1 = (const char*)(g_qfrag + (size_t)unext*QUNITW) + tid*16;
                #pragma unroll
                for (int kk = 0; kk < 2; kk++) CPA16(d1 + kk*NTHREADS*16, s1 + kk*NTHREADS*16);
                CPA_COMMIT();
                if (tid < VC) rc = g_cn2[vbase + (ci+1)*VC + tid];
            }

            const u32*   bufc = buf[cur];
            const float* csmc = csm[cur];
            int vch = vbase + ci*VC;
            #pragma unroll
            for (int uu = 0; uu < UPCH; uu++) {
                const u32* ub = bufc + uu*QUNITW;
                uint4 q0 = *(const uint4*)(ub +        lane*4);   // tile0 hi/lo
                uint4 q1 = *(const uint4*)(ub + 128 +  lane*4);   // tile1 hi/lo

                float c0=0.f,c1=0.f,c2=0.f,c3=0.f;   // tile0 dots
                float d0=0.f,d1=0.f,d2=0.f,d3=0.f;   // tile1 dots
                MMAB(c0,c1,c2,c3, xhi[0],xhi[1],xhi[2],xhi[3], q0.x, q0.y);
                MMAB(d0,d1,d2,d3, xhi[0],xhi[1],xhi[2],xhi[3], q1.x, q1.y);
                MMAB(c0,c1,c2,c3, xlo[0],xlo[1],xlo[2],xlo[3], q0.x, q0.y);
                MMAB(d0,d1,d2,d3, xlo[0],xlo[1],xlo[2],xlo[3], q1.x, q1.y);
                MMAB(c0,c1,c2,c3, xhi[0],xhi[1],xhi[2],xhi[3], q0.z, q0.w);
                MMAB(d0,d1,d2,d3, xhi[0],xhi[1],xhi[2],xhi[3], q1.z, q1.w);

                int voff = uu*16;
                float n00 = csmc[voff +     2*tig], n01 = csmc[voff +     2*tig + 1];
                float n10 = csmc[voff + 8 + 2*tig], n11 = csmc[voff + 8 + 2*tig + 1];
                int v00 = vch + voff + 2*tig,     v01 = v00 + 1;
                int v10 = vch + voff + 8 + 2*tig, v11 = v10 + 1;

                float e0;
                e0 = fmaf(-2.f, c0, n00); if (e0 < bestA) { bestA = e0; idxA = v00; }
                e0 = fmaf(-2.f, c1, n01); if (e0 < bestA) { bestA = e0; idxA = v01; }
                e0 = fmaf(-2.f, d0, n10); if (e0 < bestA) { bestA = e0; idxA = v10; }
                e0 = fmaf(-2.f, d1, n11); if (e0 < bestA) { bestA = e0; idxA = v11; }
                e0 = fmaf(-2.f, c2, n00); if (e0 < bestB) { bestB = e0; idxB = v00; }
                e0 = fmaf(-2.f, c3, n01); if (e0 < bestB) { bestB = e0; idxB = v01; }
                e0 = fmaf(-2.f, d2, n10); if (e0 < bestB) { bestB = e0; idxB = v10; }
                e0 = fmaf(-2.f, d3, n11); if (e0 < bestB) { bestB = e0; idxB = v11; }
            }
            __syncthreads();
        }

        // reduce across the 4-thread column group (tie-break: smaller index)
        #pragma unroll
        for (int off = 1; off < 4; off <<= 1) {
            float ob = __shfl_xor_sync(0xffffffffu, bestA, off);
            int   oi = __shfl_xor_sync(0xffffffffu, idxA,  off);
            if (ob < bestA || (ob == bestA && oi < idxA)) { bestA = ob; idxA = oi; }
            ob = __shfl_xor_sync(0xffffffffu, bestB, off);
            oi = __shfl_xor_sync(0xffffffffu, idxB,  off);
            if (ob < bestB || (ob == bestB && oi < idxB)) { bestB = ob; idxB = oi; }
        }
        int tokg  = tok0 + g;
        int tokg8 = tokg + 8;
        if (tig == 0) {
            g_part[(slot*2 + 0)*NTOK + tokg ] = bestA;
            g_part[(slot*2 + 1)*NTOK + tokg ] = (float)idxA;
            g_part[(slot*2 + 0)*NTOK + tokg8] = bestB;
            g_part[(slot*2 + 1)*NTOK + tokg8] = (float)idxB;
        }

        // final handshake: last CTA merges 4 slots, writes indices + x_final
        __threadfence();
        __syncthreads();
        if (tid == 0) flag = (atomicAdd(&g_ticket[tb], 1) == 4*NEVAL + 3);
        __syncthreads();
        if (flag) {
            __threadfence();
            if (tid < TPC) {
                int tok = tb*TPC + tid;
                float best = __ldcg(&g_part[0*NTOK + tok]);
                float idx  = __ldcg(&g_part[1*NTOK + tok]);
                #pragma unroll
                for (int q = 1; q < VSPLIT; q++) {
                    float bq = __ldcg(&g_part[(q*2 + 0)*NTOK + tok]);
                    float iq = __ldcg(&g_part[(q*2 + 1)*NTOK + tok]);
                    if (bq < best || (bq == best && iq < idx)) { best = bq; idx = iq; }
                }
                if (out_idx) out_idx[tok] = idx;
                if (out_x) {
                    const float4* xi4 = (const float4*)(g_x + tok*DD);
                    float4* o4 = (float4*)(out_x + tok*DD);
                    #pragma unroll
                    for (int i = 0; i < 4; i++) o4[i] = xi4[i];
                }
            }
        }
    }

    // Reset counters for next launch / graph replay (last of 4 CTAs resets;
    // the finalizer increments only after its writes, so reset is ordered after)
    if (tid == 0) {
        if (atomicAdd(&g_fin[tb], 1) == 3) {
            g_ticket[tb] = 0;
            g_done[tb]   = 0;
            g_fin[tb]    = 0;
            __threadfence();
        }
    }
}

extern "C" void kernel_launch(void* const* d_in, const int* in_sizes, int n_in,
                              void* d_out, int out_size) {
    const float* x0 = (const float*)d_in[0];
    const float* CB = (const float*)d_in[1];
    const float* W  = (const float*)d_in[2];
    const float* b  = (const float*)d_in[3];
    const float* tp = (const float*)d_in[4];

    prep_frag<<<(NUNITS*32)/256, 256>>>(W, CB);

    float* out = (float*)d_out;
    float* ox = nullptr;
    float* oi = nullptr;
    if (out_size >= NTOK*DD + NTOK) { ox = out; oi = out + NTOK*DD; }
    else if (out_size == NTOK*DD)   { ox = out; }
    else                            { oi = out; }

    velocity_persist<<<NBLOCKS, NTHREADS>>>(x0, b, tp, ox, oi);
}